// round 14
// baseline (speedup 1.0000x reference)
#include <cuda_runtime.h>
#include <cuda_fp16.h>
#include <math.h>
#include <stdint.h>

#define Bb 8
#define Tt 32
#define Gg 32
#define Ee 768
#define Hh 12
#define Ll 4
#define Ss (Tt*Gg)        // 1024
#define HD_ (Ee/Hh)       // 64
#define NR (Bb*Ss)        // 8192 rows

// weight (half) buffer offsets
#define W_IN_CNT   (Ll*3*Ee*Ee)
#define W_OUT_CNT  (Ll*Ee*Ee)
#define W_FC_CNT   (Ll*4*Ee*Ee)
#define W_PROJ_CNT (Ll*Ee*4*Ee)

// ---------------- scratch (device globals; no cudaMalloc allowed) ------------
__device__ float  g_h[NR*Ee];             // residual stream (fp32)
__device__ __half g_y[NR*Ee];             // ln / attn output (fp16)
__device__ __half g_qkv[NR*3*Ee];         // qkv (fp16)
__device__ __half g_fc[NR*4*Ee];          // mlp hidden (fp16)
__device__ __half g_wh[W_IN_CNT + W_OUT_CNT + W_FC_CNT + W_PROJ_CNT];

// ---------------- fp32 -> fp16 weight conversion ------------------------------
__global__ void f2h4_kernel(const float* __restrict__ in, __half* __restrict__ out, int n4) {
    int i = blockIdx.x * blockDim.x + threadIdx.x;
    if (i >= n4) return;
    float4 v = ((const float4*)in)[i];
    __half2 a = __floats2half2_rn(v.x, v.y);
    __half2 b = __floats2half2_rn(v.z, v.w);
    ((__half2*)out)[i * 2]     = a;
    ((__half2*)out)[i * 2 + 1] = b;
}

// ---------------- embed -------------------------------------------------------
__global__ void embed_kernel(const float* __restrict__ x,
                             const int* __restrict__ date,
                             const float* __restrict__ wpe) {
    int idx = blockIdx.x * blockDim.x + threadIdx.x;
    if (idx >= NR * Ee) return;
    int e   = idx % Ee;
    int row = idx / Ee;
    int b   = row / Ss;
    int s   = row % Ss;
    int t   = s / Gg;
    int d   = date[b * Tt + t];
    d = min(max(d, 0), 49);
    g_h[idx] = x[idx] + wpe[d * Ee + e];
}

// ---------------- layernorm: 256 thr, single pass, shuffle reduction ----------
template<typename OT>
__global__ void __launch_bounds__(256)
ln_kernel(const float* __restrict__ in, OT* __restrict__ out,
          const float* __restrict__ w, const float* __restrict__ bia) {
    const int row = blockIdx.x;
    const int tid = threadIdx.x;
    const float* xr = in + (size_t)row * Ee;
    float x0 = xr[tid], x1 = xr[tid + 256], x2 = xr[tid + 512];
    float s = x0 + x1 + x2;
    float q = x0 * x0 + x1 * x1 + x2 * x2;
    #pragma unroll
    for (int o = 16; o > 0; o >>= 1) {
        s += __shfl_xor_sync(0xffffffffu, s, o);
        q += __shfl_xor_sync(0xffffffffu, q, o);
    }
    __shared__ float sw[8], qw[8];
    if ((tid & 31) == 0) { sw[tid >> 5] = s; qw[tid >> 5] = q; }
    __syncthreads();
    s = sw[0] + sw[1] + sw[2] + sw[3] + sw[4] + sw[5] + sw[6] + sw[7];
    q = qw[0] + qw[1] + qw[2] + qw[3] + qw[4] + qw[5] + qw[6] + qw[7];
    const float inv = 1.0f / Ee;
    float mean = s * inv;
    float var  = q * inv - mean * mean;
    float rstd = rsqrtf(var + 1e-5f);
    OT* orow = out + (size_t)row * Ee;
    orow[tid]       = (OT)((x0 - mean) * rstd * w[tid]       + bia[tid]);
    orow[tid + 256] = (OT)((x1 - mean) * rstd * w[tid + 256] + bia[tid + 256]);
    orow[tid + 512] = (OT)((x2 - mean) * rstd * w[tid + 512] + bia[tid + 512]);
}

// ---------------- cp.async helpers -------------------------------------------
__device__ __forceinline__ void cp16(void* s, const void* g) {
    unsigned sa = (unsigned)__cvta_generic_to_shared(s);
    asm volatile("cp.async.ca.shared.global [%0], [%1], 16;\n" :: "r"(sa), "l"(g));
}
__device__ __forceinline__ void cp_commit() {
    asm volatile("cp.async.commit_group;\n" ::);
}
template<int N>
__device__ __forceinline__ void cp_wait() {
    asm volatile("cp.async.wait_group %0;\n" :: "n"(N));
}

// ---------------- mma / ldmatrix helpers --------------------------------------
__device__ __forceinline__ void mma16816(float c[4], const unsigned a[4],
                                         unsigned b0, unsigned b1) {
    asm volatile("mma.sync.aligned.m16n8k16.row.col.f32.f16.f16.f32 "
                 "{%0,%1,%2,%3}, {%4,%5,%6,%7}, {%8,%9}, {%0,%1,%2,%3};"
                 : "+f"(c[0]), "+f"(c[1]), "+f"(c[2]), "+f"(c[3])
                 : "r"(a[0]), "r"(a[1]), "r"(a[2]), "r"(a[3]), "r"(b0), "r"(b1));
}
__device__ __forceinline__ void ldsm_x4(unsigned &r0, unsigned &r1, unsigned &r2,
                                        unsigned &r3, unsigned addr) {
    asm volatile("ldmatrix.sync.aligned.m8n8.x4.shared.b16 {%0,%1,%2,%3}, [%4];"
                 : "=r"(r0), "=r"(r1), "=r"(r2), "=r"(r3) : "r"(addr));
}
__device__ __forceinline__ void ldsm_x2_t(unsigned &r0, unsigned &r1, const void* p) {
    unsigned a = (unsigned)__cvta_generic_to_shared(p);
    asm volatile("ldmatrix.sync.aligned.m8n8.x2.trans.shared.b16 {%0,%1}, [%2];"
                 : "=r"(r0), "=r"(r1) : "r"(a));
}
// exact tanh via e^x: tanh(u) = 1 - 2/(1+exp(2u)); saturates correctly.
__device__ __forceinline__ float fast_gelu(float v) {
    float u = 0.7978845608028654f * (v + 0.044715f * v * v * v);
    float t = 1.0f - 2.0f / (1.0f + __expf(2.0f * u));
    return 0.5f * v * (1.0f + t);
}

// ---------------- fp16 HMMA GEMM, BK=64, SW128 smem + ldmatrix operands -------
template<int WN, int EPI>
__global__ void __launch_bounds__(WN * 64)
gemm_h(const __half* __restrict__ A, const __half* __restrict__ W,
       const float* __restrict__ bias, void* __restrict__ Cv,
       int M, int N, int K) {
    constexpr int BN  = WN * 64;
    constexpr int NTH = WN * 64;
    constexpr unsigned ASTAGE = 16384u;
    constexpr unsigned WOFF   = 2 * ASTAGE;
    constexpr unsigned WSTAGE = (unsigned)BN * 128u;
    extern __shared__ __align__(128) char sm[];
    const unsigned sb = (unsigned)__cvta_generic_to_shared(sm);

    const int m0 = blockIdx.y * 128;
    const int n0 = blockIdx.x * BN;
    const int tid  = threadIdx.x;
    const int lane = tid & 31;
    const int wid  = tid >> 5;
    const int wm = (wid & 1) * 64;
    const int wn = (wid >> 1) * 64;
    const int gr = lane >> 2;
    const int gc = lane & 3;

    const int g = lane >> 3, j = lane & 7;
    const int arowoff = ((g & 1) << 3) + j;
    const int acoff   = g >> 1;
    const int browoff = ((g >> 1) << 3) + j;
    const int bcoff   = g & 1;

    const int KT = K >> 6;

    float acc[4][8][4];
    #pragma unroll
    for (int tm = 0; tm < 4; tm++)
        #pragma unroll
        for (int tn = 0; tn < 8; tn++)
            #pragma unroll
            for (int i = 0; i < 4; i++) acc[tm][tn][i] = 0.f;

    #define LOAD_TILE(st, kt_) do {                                               \
        int k0 = (kt_) << 6;                                                      \
        _Pragma("unroll")                                                         \
        for (int i = tid; i < (128 + BN) * 8; i += NTH) {                         \
            int r = i >> 3, c = i & 7;                                            \
            if (r < 128) {                                                        \
                cp16(sm + (st) * ASTAGE + r * 128 + ((c ^ (r & 7)) * 16),         \
                     &A[(size_t)(m0 + r) * K + k0 + c * 8]);                      \
            } else {                                                              \
                int rr = r - 128;                                                 \
                cp16(sm + WOFF + (st) * WSTAGE + rr * 128 + ((c ^ (rr & 7)) * 16),\
                     &W[(size_t)(n0 + rr) * K + k0 + c * 8]);                     \
            }                                                                     \
        }                                                                         \
    } while (0)

    LOAD_TILE(0, 0); cp_commit();
    if (KT > 1) LOAD_TILE(1, 1);
    cp_commit();

    for (int kt = 0; kt < KT; kt++) {
        const int st = kt & 1;
        cp_wait<1>();
        __syncthreads();
        const unsigned aSt = sb + st * ASTAGE;
        const unsigned wSt = sb + WOFF + st * WSTAGE;

        #pragma unroll
        for (int kk = 0; kk < 64; kk += 16) {
            const int cbase = kk >> 3;
            unsigned af[4][4], bf[8][2];
            #pragma unroll
            for (int tm = 0; tm < 4; tm++) {
                int row = wm + tm * 16 + arowoff;
                unsigned addr = aSt + row * 128 + (((cbase + acoff) ^ (row & 7)) << 4);
                ldsm_x4(af[tm][0], af[tm][1], af[tm][2], af[tm][3], addr);
            }
            #pragma unroll
            for (int tp = 0; tp < 4; tp++) {
                int row = wn + tp * 16 + browoff;
                unsigned addr = wSt + row * 128 + (((cbase + bcoff) ^ (row & 7)) << 4);
                ldsm_x4(bf[2 * tp][0], bf[2 * tp][1], bf[2 * tp + 1][0], bf[2 * tp + 1][1], addr);
            }
            #pragma unroll
            for (int tm = 0; tm < 4; tm++)
                #pragma unroll
                for (int tn = 0; tn < 8; tn++)
                    mma16816(acc[tm][tn], af[tm], bf[tn][0], bf[tn][1]);
        }
        __syncthreads();
        if (kt + 2 < KT) LOAD_TILE(st, kt + 2);
        cp_commit();
    }
    #undef LOAD_TILE

    #pragma unroll
    for (int tm = 0; tm < 4; tm++) {
        #pragma unroll
        for (int tn = 0; tn < 8; tn++) {
            int m = m0 + wm + tm * 16 + gr;
            int n = n0 + wn + tn * 8 + gc * 2;
            float b0 = bias[n], b1 = bias[n + 1];
            #pragma unroll
            for (int half_ = 0; half_ < 2; half_++) {
                int mm = m + half_ * 8;
                float v0 = acc[tm][tn][half_ * 2 + 0] + b0;
                float v1 = acc[tm][tn][half_ * 2 + 1] + b1;
                size_t o = (size_t)mm * N + n;
                if (EPI == 0) {
                    *(__half2*)((__half*)Cv + o) = __floats2half2_rn(v0, v1);
                } else if (EPI == 1) {
                    *(__half2*)((__half*)Cv + o) =
                        __floats2half2_rn(fast_gelu(v0), fast_gelu(v1));
                } else {
                    float* C = (float*)Cv;
                    float2 cc = *(float2*)&C[o];
                    cc.x += v0; cc.y += v1;
                    *(float2*)&C[o] = cc;
                }
            }
        }
    }
}

// ---------------- tensor-core flash attention, 64-query tiles -----------------
// One block per (b, h, pair of T-blocks); 4 warps, each owns 16 q-rows.
// Warps 0-1: q rows [p*64, p*64+32) -> kmax = (2p+1)*32  (nkt_low tiles)
// Warps 2-3: q rows [p*64+32, ...)  -> kmax = (2p+2)*32  (one extra tile)
__global__ void __launch_bounds__(128)
attn_mma(const __half* __restrict__ qkv, __half* __restrict__ out) {
    const int pair = (Tt / 2 - 1) - blockIdx.x;   // heavy tiles first
    const int h = blockIdx.y, b = blockIdx.z;
    const int q0 = pair * 64;
    const int nkt_low  = 2 * pair + 1;
    const int nkt_high = nkt_low + 1;
    const int tid  = threadIdx.x;
    const int lane = tid & 31;
    const int warp = tid >> 5;
    const int gr = lane >> 2, gc = lane & 3;
    const int mw = warp * 16;
    const int nkt_w = (warp < 2) ? nkt_low : nkt_high;

    __shared__ __half Qs[64][72];
    __shared__ __half Ks[2][32][72];
    __shared__ __half Vs[2][32][72];

    const size_t stride = 3 * Ee;
    const size_t qbase = (size_t)(b * Ss + q0) * stride + h * HD_;

    // prologue: async K/V tile 0  (32 rows; 128 thr x 16B = 2 rows-pass)
    {
        size_t kb = (size_t)(b * Ss) * stride + Ee + h * HD_;
        #pragma unroll
        for (int i = 0; i < 2; i++) {
            int t = tid + i * 128; int r = t >> 3, c = (t & 7) * 8;
            cp16(&Ks[0][r][c], &qkv[kb + (size_t)r * stride + c]);
            cp16(&Vs[0][r][c], &qkv[kb + Ee + (size_t)r * stride + c]);
        }
        cp_commit();
    }
    // Q tile [64 x 64] direct
    #pragma unroll
    for (int i = 0; i < 4; i++) {
        int t = tid + i * 128; int r = t >> 3, c = (t & 7) * 8;
        *(uint4*)&Qs[r][c] = *(const uint4*)&qkv[qbase + (size_t)r * stride + c];
    }
    __syncthreads();

    unsigned qa[4][4];
    #pragma unroll
    for (int kc = 0; kc < 4; kc++) {
        qa[kc][0] = *(const unsigned*)&Qs[mw + gr][kc * 16 + gc * 2];
        qa[kc][1] = *(const unsigned*)&Qs[mw + gr + 8][kc * 16 + gc * 2];
        qa[kc][2] = *(const unsigned*)&Qs[mw + gr][kc * 16 + gc * 2 + 8];
        qa[kc][3] = *(const unsigned*)&Qs[mw + gr + 8][kc * 16 + gc * 2 + 8];
    }

    float m0r = -1e30f, m1r = -1e30f, l0 = 0.f, l1 = 0.f;
    float oacc[8][4];
    #pragma unroll
    for (int vn = 0; vn < 8; vn++)
        #pragma unroll
        for (int c = 0; c < 4; c++) oacc[vn][c] = 0.f;

    for (int kt = 0; kt < nkt_high; kt++) {
        const int st = kt & 1;
        cp_wait<0>();
        __syncthreads();
        if (kt + 1 < nkt_high) {
            size_t kb = (size_t)(b * Ss + (kt + 1) * Gg) * stride + Ee + h * HD_;
            #pragma unroll
            for (int i = 0; i < 2; i++) {
                int t = tid + i * 128; int r = t >> 3, c = (t & 7) * 8;
                cp16(&Ks[st ^ 1][r][c], &qkv[kb + (size_t)r * stride + c]);
                cp16(&Vs[st ^ 1][r][c], &qkv[kb + Ee + (size_t)r * stride + c]);
            }
            cp_commit();
        }
        if (kt >= nkt_w) continue;   // warps 0-1 skip the final (odd) tile

        float s[4][4];
        #pragma unroll
        for (int jn = 0; jn < 4; jn++)
            s[jn][0] = s[jn][1] = s[jn][2] = s[jn][3] = 0.f;
        #pragma unroll
        for (int kc = 0; kc < 4; kc++) {
            #pragma unroll
            for (int jn = 0; jn < 4; jn++) {
                unsigned b0 = *(const unsigned*)&Ks[st][jn * 8 + gr][kc * 16 + gc * 2];
                unsigned b1 = *(const unsigned*)&Ks[st][jn * 8 + gr][kc * 16 + gc * 2 + 8];
                mma16816(s[jn], qa[kc], b0, b1);
            }
        }

        float mt0 = -1e30f, mt1 = -1e30f;
        #pragma unroll
        for (int jn = 0; jn < 4; jn++) {
            s[jn][0] *= 0.125f; s[jn][1] *= 0.125f;
            s[jn][2] *= 0.125f; s[jn][3] *= 0.125f;
            mt0 = fmaxf(mt0, fmaxf(s[jn][0], s[jn][1]));
            mt1 = fmaxf(mt1, fmaxf(s[jn][2], s[jn][3]));
        }
        mt0 = fmaxf(mt0, __shfl_xor_sync(0xffffffffu, mt0, 1));
        mt0 = fmaxf(mt0, __shfl_xor_sync(0xffffffffu, mt0, 2));
        mt1 = fmaxf(mt1, __shfl_xor_sync(0xffffffffu, mt1, 1));
        mt1 = fmaxf(mt1, __shfl_xor_sync(0xffffffffu, mt1, 2));
        float mn0 = fmaxf(m0r, mt0), mn1 = fmaxf(m1r, mt1);
        float c0 = __expf(m0r - mn0), c1 = __expf(m1r - mn1);
        m0r = mn0; m1r = mn1;
        float rs0 = 0.f, rs1 = 0.f;
        #pragma unroll
        for (int jn = 0; jn < 4; jn++) {
            s[jn][0] = __expf(s[jn][0] - mn0); s[jn][1] = __expf(s[jn][1] - mn0);
            s[jn][2] = __expf(s[jn][2] - mn1); s[jn][3] = __expf(s[jn][3] - mn1);
            rs0 += s[jn][0] + s[jn][1];
            rs1 += s[jn][2] + s[jn][3];
        }
        rs0 += __shfl_xor_sync(0xffffffffu, rs0, 1);
        rs0 += __shfl_xor_sync(0xffffffffu, rs0, 2);
        rs1 += __shfl_xor_sync(0xffffffffu, rs1, 1);
        rs1 += __shfl_xor_sync(0xffffffffu, rs1, 2);
        l0 = l0 * c0 + rs0;
        l1 = l1 * c1 + rs1;

        unsigned pa[2][4];
        #pragma unroll
        for (int pc = 0; pc < 2; pc++) {
            __half2 t0 = __floats2half2_rn(s[2 * pc][0],     s[2 * pc][1]);
            __half2 t1 = __floats2half2_rn(s[2 * pc][2],     s[2 * pc][3]);
            __half2 t2 = __floats2half2_rn(s[2 * pc + 1][0], s[2 * pc + 1][1]);
            __half2 t3 = __floats2half2_rn(s[2 * pc + 1][2], s[2 * pc + 1][3]);
            pa[pc][0] = *(unsigned*)&t0; pa[pc][1] = *(unsigned*)&t1;
            pa[pc][2] = *(unsigned*)&t2; pa[pc][3] = *(unsigned*)&t3;
        }

        #pragma unroll
        for (int vn = 0; vn < 8; vn++) {
            oacc[vn][0] *= c0; oacc[vn][1] *= c0;
            oacc[vn][2] *= c1; oacc[vn][3] *= c1;
        }
        #pragma unroll
        for (int pc = 0; pc < 2; pc++) {
            #pragma unroll
            for (int vn = 0; vn < 8; vn++) {
                unsigned b0, b1;
                ldsm_x2_t(b0, b1, &Vs[st][pc * 16 + (lane & 15)][vn * 8]);
                mma16816(oacc[vn], pa[pc], b0, b1);
            }
        }
    }

    float inv0 = 1.f / l0, inv1 = 1.f / l1;
    size_t r0 = (size_t)(b * Ss + q0 + mw + gr) * Ee + h * HD_;
    size_t r1 = r0 + (size_t)8 * Ee;
    #pragma unroll
    for (int vn = 0; vn < 8; vn++) {
        int col = vn * 8 + gc * 2;
        *(__half2*)&out[r0 + col] = __floats2half2_rn(oacc[vn][0] * inv0, oacc[vn][1] * inv0);
        *(__half2*)&out[r1 + col] = __floats2half2_rn(oacc[vn][2] * inv1, oacc[vn][3] * inv1);
    }
}

// ---------------- host orchestration -----------------------------------------
extern "C" void kernel_launch(void* const* d_in, const int* in_sizes, int n_in,
                              void* d_out, int out_size) {
    const float* x      = (const float*)d_in[0];
    const int*   date   = (const int*)  d_in[1];
    const float* wpe    = (const float*)d_in[2];
    const float* ln1_w  = (const float*)d_in[3];
    const float* ln1_b  = (const float*)d_in[4];
    const float* in_w   = (const float*)d_in[5];
    const float* in_b   = (const float*)d_in[6];
    const float* out_w  = (const float*)d_in[7];
    const float* out_b  = (const float*)d_in[8];
    const float* ln2_w  = (const float*)d_in[9];
    const float* ln2_b  = (const float*)d_in[10];
    const float* fc_w   = (const float*)d_in[11];
    const float* fc_b   = (const float*)d_in[12];
    const float* proj_w = (const float*)d_in[13];
    const float* proj_b = (const float*)d_in[14];
    const float* lnf_w  = (const float*)d_in[15];
    const float* lnf_b  = (const float*)d_in[16];
    float* out = (float*)d_out;

    float  *h;
    __half *y, *qkv, *fc, *wh;
    cudaGetSymbolAddress((void**)&h,   g_h);
    cudaGetSymbolAddress((void**)&y,   g_y);
    cudaGetSymbolAddress((void**)&qkv, g_qkv);
    cudaGetSymbolAddress((void**)&fc,  g_fc);
    cudaGetSymbolAddress((void**)&wh,  g_wh);

    __half* in_wh   = wh;
    __half* out_wh  = wh + W_IN_CNT;
    __half* fc_wh   = wh + W_IN_CNT + W_OUT_CNT;
    __half* proj_wh = wh + W_IN_CNT + W_OUT_CNT + W_FC_CNT;

    const int SMEM_WIDE = 98304, SMEM_NARROW = 65536;
    cudaFuncSetAttribute(gemm_h<4, 0>, cudaFuncAttributeMaxDynamicSharedMemorySize, SMEM_WIDE);
    cudaFuncSetAttribute(gemm_h<4, 1>, cudaFuncAttributeMaxDynamicSharedMemorySize, SMEM_WIDE);
    cudaFuncSetAttribute(gemm_h<2, 2>, cudaFuncAttributeMaxDynamicSharedMemorySize, SMEM_NARROW);

    f2h4_kernel<<<(W_IN_CNT / 4 + 255) / 256, 256>>>(in_w, in_wh, W_IN_CNT / 4);
    f2h4_kernel<<<(W_OUT_CNT / 4 + 255) / 256, 256>>>(out_w, out_wh, W_OUT_CNT / 4);
    f2h4_kernel<<<(W_FC_CNT / 4 + 255) / 256, 256>>>(fc_w, fc_wh, W_FC_CNT / 4);
    f2h4_kernel<<<(W_PROJ_CNT / 4 + 255) / 256, 256>>>(proj_w, proj_wh, W_PROJ_CNT / 4);

    embed_kernel<<<(NR * Ee + 255) / 256, 256>>>(x, date, wpe);

    for (int l = 0; l < Ll; l++) {
        ln_kernel<__half><<<NR, 256>>>(h, y, ln1_w + (size_t)l * Ee, ln1_b + (size_t)l * Ee);
        gemm_h<4, 0><<<dim3(3 * Ee / 256, NR / 128), 256, SMEM_WIDE>>>(
            y, in_wh + (size_t)l * 3 * Ee * Ee, in_b + (size_t)l * 3 * Ee, qkv,
            NR, 3 * Ee, Ee);
        attn_mma<<<dim3(Tt / 2, Hh, Bb), 128>>>(qkv, y);
        gemm_h<2, 2><<<dim3(Ee / 128, NR / 128), 128, SMEM_NARROW>>>(
            y, out_wh + (size_t)l * Ee * Ee, out_b + (size_t)l * Ee, h,
            NR, Ee, Ee);
        ln_kernel<__half><<<NR, 256>>>(h, y, ln2_w + (size_t)l * Ee, ln2_b + (size_t)l * Ee);
        gemm_h<4, 1><<<dim3(4 * Ee / 256, NR / 128), 256, SMEM_WIDE>>>(
            y, fc_wh + (size_t)l * 4 * Ee * Ee, fc_b + (size_t)l * 4 * Ee, fc,
            NR, 4 * Ee, Ee);
        gemm_h<2, 2><<<dim3(Ee / 128, NR / 128), 128, SMEM_NARROW>>>(
            fc, proj_wh + (size_t)l * Ee * 4 * Ee, proj_b + (size_t)l * Ee, h,
            NR, Ee, 4 * Ee);
    }

    ln_kernel<float><<<NR, 256>>>(h, out, lnf_w, lnf_b);
}

// round 15
// speedup vs baseline: 1.0432x; 1.0432x over previous
#include <cuda_runtime.h>
#include <cuda_fp16.h>
#include <math.h>
#include <stdint.h>

#define Bb 8
#define Tt 32
#define Gg 32
#define Ee 768
#define Hh 12
#define Ll 4
#define Ss (Tt*Gg)        // 1024
#define HD_ (Ee/Hh)       // 64
#define NR (Bb*Ss)        // 8192 rows

// weight (half) buffer offsets
#define W_IN_CNT   (Ll*3*Ee*Ee)
#define W_OUT_CNT  (Ll*Ee*Ee)
#define W_FC_CNT   (Ll*4*Ee*Ee)
#define W_PROJ_CNT (Ll*Ee*4*Ee)

// ---------------- scratch (device globals; no cudaMalloc allowed) ------------
__device__ float  g_h[NR*Ee];             // residual stream (fp32)
__device__ __half g_y[NR*Ee];             // ln / attn output (fp16)
__device__ __half g_qkv[NR*3*Ee];         // qkv (fp16)
__device__ __half g_fc[NR*4*Ee];          // mlp hidden (fp16)
__device__ __half g_wh[W_IN_CNT + W_OUT_CNT + W_FC_CNT + W_PROJ_CNT];

// ---------------- fp32 -> fp16 weight conversion ------------------------------
__global__ void f2h4_kernel(const float* __restrict__ in, __half* __restrict__ out, int n4) {
    int i = blockIdx.x * blockDim.x + threadIdx.x;
    if (i >= n4) return;
    float4 v = ((const float4*)in)[i];
    __half2 a = __floats2half2_rn(v.x, v.y);
    __half2 b = __floats2half2_rn(v.z, v.w);
    ((__half2*)out)[i * 2]     = a;
    ((__half2*)out)[i * 2 + 1] = b;
}

// ---------------- embed -------------------------------------------------------
__global__ void embed_kernel(const float* __restrict__ x,
                             const int* __restrict__ date,
                             const float* __restrict__ wpe) {
    int idx = blockIdx.x * blockDim.x + threadIdx.x;
    if (idx >= NR * Ee) return;
    int e   = idx % Ee;
    int row = idx / Ee;
    int b   = row / Ss;
    int s   = row % Ss;
    int t   = s / Gg;
    int d   = date[b * Tt + t];
    d = min(max(d, 0), 49);
    g_h[idx] = x[idx] + wpe[d * Ee + e];
}

// ---------------- layernorm: 256 thr, single pass, shuffle reduction ----------
template<typename OT>
__global__ void __launch_bounds__(256)
ln_kernel(const float* __restrict__ in, OT* __restrict__ out,
          const float* __restrict__ w, const float* __restrict__ bia) {
    const int row = blockIdx.x;
    const int tid = threadIdx.x;
    const float* xr = in + (size_t)row * Ee;
    float x0 = xr[tid], x1 = xr[tid + 256], x2 = xr[tid + 512];
    float s = x0 + x1 + x2;
    float q = x0 * x0 + x1 * x1 + x2 * x2;
    #pragma unroll
    for (int o = 16; o > 0; o >>= 1) {
        s += __shfl_xor_sync(0xffffffffu, s, o);
        q += __shfl_xor_sync(0xffffffffu, q, o);
    }
    __shared__ float sw[8], qw[8];
    if ((tid & 31) == 0) { sw[tid >> 5] = s; qw[tid >> 5] = q; }
    __syncthreads();
    s = sw[0] + sw[1] + sw[2] + sw[3] + sw[4] + sw[5] + sw[6] + sw[7];
    q = qw[0] + qw[1] + qw[2] + qw[3] + qw[4] + qw[5] + qw[6] + qw[7];
    const float inv = 1.0f / Ee;
    float mean = s * inv;
    float var  = q * inv - mean * mean;
    float rstd = rsqrtf(var + 1e-5f);
    OT* orow = out + (size_t)row * Ee;
    orow[tid]       = (OT)((x0 - mean) * rstd * w[tid]       + bia[tid]);
    orow[tid + 256] = (OT)((x1 - mean) * rstd * w[tid + 256] + bia[tid + 256]);
    orow[tid + 512] = (OT)((x2 - mean) * rstd * w[tid + 512] + bia[tid + 512]);
}

// ---------------- cp.async helpers -------------------------------------------
__device__ __forceinline__ void cp16(void* s, const void* g) {
    unsigned sa = (unsigned)__cvta_generic_to_shared(s);
    asm volatile("cp.async.ca.shared.global [%0], [%1], 16;\n" :: "r"(sa), "l"(g));
}
__device__ __forceinline__ void cp_commit() {
    asm volatile("cp.async.commit_group;\n" ::);
}
template<int N>
__device__ __forceinline__ void cp_wait() {
    asm volatile("cp.async.wait_group %0;\n" :: "n"(N));
}

// ---------------- mma / ldmatrix helpers --------------------------------------
__device__ __forceinline__ void mma16816(float c[4], const unsigned a[4],
                                         unsigned b0, unsigned b1) {
    asm volatile("mma.sync.aligned.m16n8k16.row.col.f32.f16.f16.f32 "
                 "{%0,%1,%2,%3}, {%4,%5,%6,%7}, {%8,%9}, {%0,%1,%2,%3};"
                 : "+f"(c[0]), "+f"(c[1]), "+f"(c[2]), "+f"(c[3])
                 : "r"(a[0]), "r"(a[1]), "r"(a[2]), "r"(a[3]), "r"(b0), "r"(b1));
}
__device__ __forceinline__ void ldsm_x4(unsigned &r0, unsigned &r1, unsigned &r2,
                                        unsigned &r3, unsigned addr) {
    asm volatile("ldmatrix.sync.aligned.m8n8.x4.shared.b16 {%0,%1,%2,%3}, [%4];"
                 : "=r"(r0), "=r"(r1), "=r"(r2), "=r"(r3) : "r"(addr));
}
__device__ __forceinline__ void ldsm_x2_t(unsigned &r0, unsigned &r1, const void* p) {
    unsigned a = (unsigned)__cvta_generic_to_shared(p);
    asm volatile("ldmatrix.sync.aligned.m8n8.x2.trans.shared.b16 {%0,%1}, [%2];"
                 : "=r"(r0), "=r"(r1) : "r"(a));
}
// exact tanh via e^x: tanh(u) = 1 - 2/(1+exp(2u)); saturates correctly.
__device__ __forceinline__ float fast_gelu(float v) {
    float u = 0.7978845608028654f * (v + 0.044715f * v * v * v);
    float t = 1.0f - 2.0f / (1.0f + __expf(2.0f * u));
    return 0.5f * v * (1.0f + t);
}

// ---------------- fp16 HMMA GEMM, BK=64, SW128 smem, 3-stage pipeline ---------
// C[m,n] (op)= sum_k A[m,k]*W[n,k] + bias[n];  A,W fp16 K-major; fp32 acc.
// BM=128, BN=WN*64, threads=WN*64 (2 x WN warps), warp tile 64x64.
// One __syncthreads per k-tile; 2 k-tiles of cp.async in flight.
// EPI: 0 = store half, 1 = NewGELU -> half, 2 = add fp32 into C (residual)
template<int WN, int EPI>
__global__ void __launch_bounds__(WN * 64)
gemm_h(const __half* __restrict__ A, const __half* __restrict__ W,
       const float* __restrict__ bias, void* __restrict__ Cv,
       int M, int N, int K) {
    constexpr int BN  = WN * 64;
    constexpr int NTH = WN * 64;
    constexpr unsigned ASTAGE = 16384u;               // 128 rows * 128 B
    constexpr unsigned WOFF   = 3 * ASTAGE;           // A stages end
    constexpr unsigned WSTAGE = (unsigned)BN * 128u;
    extern __shared__ __align__(128) char sm[];
    const unsigned sb = (unsigned)__cvta_generic_to_shared(sm);

    const int m0 = blockIdx.y * 128;
    const int n0 = blockIdx.x * BN;
    const int tid  = threadIdx.x;
    const int lane = tid & 31;
    const int wid  = tid >> 5;
    const int wm = (wid & 1) * 64;
    const int wn = (wid >> 1) * 64;
    const int gr = lane >> 2;
    const int gc = lane & 3;

    const int g = lane >> 3, j = lane & 7;
    const int arowoff = ((g & 1) << 3) + j;
    const int acoff   = g >> 1;
    const int browoff = ((g >> 1) << 3) + j;
    const int bcoff   = g & 1;

    const int KT = K >> 6;

    float acc[4][8][4];
    #pragma unroll
    for (int tm = 0; tm < 4; tm++)
        #pragma unroll
        for (int tn = 0; tn < 8; tn++)
            #pragma unroll
            for (int i = 0; i < 4; i++) acc[tm][tn][i] = 0.f;

    #define LOAD_TILE(st, kt_) do {                                               \
        int k0 = (kt_) << 6;                                                      \
        _Pragma("unroll")                                                         \
        for (int i = tid; i < (128 + BN) * 8; i += NTH) {                         \
            int r = i >> 3, c = i & 7;                                            \
            if (r < 128) {                                                        \
                cp16(sm + (st) * ASTAGE + r * 128 + ((c ^ (r & 7)) * 16),         \
                     &A[(size_t)(m0 + r) * K + k0 + c * 8]);                      \
            } else {                                                              \
                int rr = r - 128;                                                 \
                cp16(sm + WOFF + (st) * WSTAGE + rr * 128 + ((c ^ (rr & 7)) * 16),\
                     &W[(size_t)(n0 + rr) * K + k0 + c * 8]);                     \
            }                                                                     \
        }                                                                         \
    } while (0)

    LOAD_TILE(0, 0); cp_commit();
    if (KT > 1) LOAD_TILE(1, 1);
    cp_commit();

    for (int kt = 0; kt < KT; kt++) {
        const int buf = kt % 3;
        cp_wait<1>();          // k-tile kt resident (kt+1 still in flight)
        __syncthreads();       // all warps finished tile kt-1 (stage (kt+2)%3 free)
        if (kt + 2 < KT) LOAD_TILE((kt + 2) % 3, kt + 2);
        cp_commit();

        const unsigned aSt = sb + buf * ASTAGE;
        const unsigned wSt = sb + WOFF + buf * WSTAGE;

        #pragma unroll
        for (int kk = 0; kk < 64; kk += 16) {
            const int cbase = kk >> 3;
            unsigned af[4][4], bf[8][2];
            #pragma unroll
            for (int tm = 0; tm < 4; tm++) {
                int row = wm + tm * 16 + arowoff;
                unsigned addr = aSt + row * 128 + (((cbase + acoff) ^ (row & 7)) << 4);
                ldsm_x4(af[tm][0], af[tm][1], af[tm][2], af[tm][3], addr);
            }
            #pragma unroll
            for (int tp = 0; tp < 4; tp++) {
                int row = wn + tp * 16 + browoff;
                unsigned addr = wSt + row * 128 + (((cbase + bcoff) ^ (row & 7)) << 4);
                ldsm_x4(bf[2 * tp][0], bf[2 * tp][1], bf[2 * tp + 1][0], bf[2 * tp + 1][1], addr);
            }
            #pragma unroll
            for (int tm = 0; tm < 4; tm++)
                #pragma unroll
                for (int tn = 0; tn < 8; tn++)
                    mma16816(acc[tm][tn], af[tm], bf[tn][0], bf[tn][1]);
        }
    }
    #undef LOAD_TILE

    #pragma unroll
    for (int tm = 0; tm < 4; tm++) {
        #pragma unroll
        for (int tn = 0; tn < 8; tn++) {
            int m = m0 + wm + tm * 16 + gr;
            int n = n0 + wn + tn * 8 + gc * 2;
            float b0 = bias[n], b1 = bias[n + 1];
            #pragma unroll
            for (int half_ = 0; half_ < 2; half_++) {
                int mm = m + half_ * 8;
                float v0 = acc[tm][tn][half_ * 2 + 0] + b0;
                float v1 = acc[tm][tn][half_ * 2 + 1] + b1;
                size_t o = (size_t)mm * N + n;
                if (EPI == 0) {
                    *(__half2*)((__half*)Cv + o) = __floats2half2_rn(v0, v1);
                } else if (EPI == 1) {
                    *(__half2*)((__half*)Cv + o) =
                        __floats2half2_rn(fast_gelu(v0), fast_gelu(v1));
                } else {
                    float* C = (float*)Cv;
                    float2 cc = *(float2*)&C[o];
                    cc.x += v0; cc.y += v1;
                    *(float2*)&C[o] = cc;
                }
            }
        }
    }
}

// ---------------- tensor-core flash attention (R13 config) --------------------
// One block per (b, h, 32-query T-block); 2 warps, each owns 16 q-rows.
__global__ void __launch_bounds__(64)
attn_mma(const __half* __restrict__ qkv, __half* __restrict__ out) {
    const int tq = (Tt - 1) - blockIdx.x;    // heavy tiles first
    const int h = blockIdx.y, b = blockIdx.z;
    const int q0 = tq * Gg;
    const int nkt = tq + 1;
    const int tid  = threadIdx.x;
    const int lane = tid & 31;
    const int warp = tid >> 5;
    const int gr = lane >> 2, gc = lane & 3;
    const int mw = warp * 16;

    __shared__ __half Qs[32][72];
    __shared__ __half Ks[2][32][72];
    __shared__ __half Vs[2][32][72];

    const size_t stride = 3 * Ee;
    const size_t qbase = (size_t)(b * Ss + q0) * stride + h * HD_;

    {
        size_t kb = (size_t)(b * Ss) * stride + Ee + h * HD_;
        #pragma unroll
        for (int i = 0; i < 4; i++) {
            int t = tid + i * 64; int r = t >> 3, c = (t & 7) * 8;
            cp16(&Ks[0][r][c], &qkv[kb + (size_t)r * stride + c]);
            cp16(&Vs[0][r][c], &qkv[kb + Ee + (size_t)r * stride + c]);
        }
        cp_commit();
    }
    #pragma unroll
    for (int i = 0; i < 4; i++) {
        int t = tid + i * 64; int r = t >> 3, c = (t & 7) * 8;
        *(uint4*)&Qs[r][c] = *(const uint4*)&qkv[qbase + (size_t)r * stride + c];
    }
    __syncthreads();

    unsigned qa[4][4];
    #pragma unroll
    for (int kc = 0; kc < 4; kc++) {
        qa[kc][0] = *(const unsigned*)&Qs[mw + gr][kc * 16 + gc * 2];
        qa[kc][1] = *(const unsigned*)&Qs[mw + gr + 8][kc * 16 + gc * 2];
        qa[kc][2] = *(const unsigned*)&Qs[mw + gr][kc * 16 + gc * 2 + 8];
        qa[kc][3] = *(const unsigned*)&Qs[mw + gr + 8][kc * 16 + gc * 2 + 8];
    }

    float m0r = -1e30f, m1r = -1e30f, l0 = 0.f, l1 = 0.f;
    float oacc[8][4];
    #pragma unroll
    for (int vn = 0; vn < 8; vn++)
        #pragma unroll
        for (int c = 0; c < 4; c++) oacc[vn][c] = 0.f;

    for (int kt = 0; kt < nkt; kt++) {
        const int st = kt & 1;
        cp_wait<0>();
        __syncthreads();
        if (kt + 1 < nkt) {
            size_t kb = (size_t)(b * Ss + (kt + 1) * Gg) * stride + Ee + h * HD_;
            #pragma unroll
            for (int i = 0; i < 4; i++) {
                int t = tid + i * 64; int r = t >> 3, c = (t & 7) * 8;
                cp16(&Ks[st ^ 1][r][c], &qkv[kb + (size_t)r * stride + c]);
                cp16(&Vs[st ^ 1][r][c], &qkv[kb + Ee + (size_t)r * stride + c]);
            }
            cp_commit();
        }

        float s[4][4];
        #pragma unroll
        for (int jn = 0; jn < 4; jn++)
            s[jn][0] = s[jn][1] = s[jn][2] = s[jn][3] = 0.f;
        #pragma unroll
        for (int kc = 0; kc < 4; kc++) {
            #pragma unroll
            for (int jn = 0; jn < 4; jn++) {
                unsigned b0 = *(const unsigned*)&Ks[st][jn * 8 + gr][kc * 16 + gc * 2];
                unsigned b1 = *(const unsigned*)&Ks[st][jn * 8 + gr][kc * 16 + gc * 2 + 8];
                mma16816(s[jn], qa[kc], b0, b1);
            }
        }

        float mt0 = -1e30f, mt1 = -1e30f;
        #pragma unroll
        for (int jn = 0; jn < 4; jn++) {
            s[jn][0] *= 0.125f; s[jn][1] *= 0.125f;
            s[jn][2] *= 0.125f; s[jn][3] *= 0.125f;
            mt0 = fmaxf(mt0, fmaxf(s[jn][0], s[jn][1]));
            mt1 = fmaxf(mt1, fmaxf(s[jn][2], s[jn][3]));
        }
        mt0 = fmaxf(mt0, __shfl_xor_sync(0xffffffffu, mt0, 1));
        mt0 = fmaxf(mt0, __shfl_xor_sync(0xffffffffu, mt0, 2));
        mt1 = fmaxf(mt1, __shfl_xor_sync(0xffffffffu, mt1, 1));
        mt1 = fmaxf(mt1, __shfl_xor_sync(0xffffffffu, mt1, 2));
        float mn0 = fmaxf(m0r, mt0), mn1 = fmaxf(m1r, mt1);
        float c0 = __expf(m0r - mn0), c1 = __expf(m1r - mn1);
        m0r = mn0; m1r = mn1;
        float rs0 = 0.f, rs1 = 0.f;
        #pragma unroll
        for (int jn = 0; jn < 4; jn++) {
            s[jn][0] = __expf(s[jn][0] - mn0); s[jn][1] = __expf(s[jn][1] - mn0);
            s[jn][2] = __expf(s[jn][2] - mn1); s[jn][3] = __expf(s[jn][3] - mn1);
            rs0 += s[jn][0] + s[jn][1];
            rs1 += s[jn][2] + s[jn][3];
        }
        rs0 += __shfl_xor_sync(0xffffffffu, rs0, 1);
        rs0 += __shfl_xor_sync(0xffffffffu, rs0, 2);
        rs1 += __shfl_xor_sync(0xffffffffu, rs1, 1);
        rs1 += __shfl_xor_sync(0xffffffffu, rs1, 2);
        l0 = l0 * c0 + rs0;
        l1 = l1 * c1 + rs1;

        unsigned pa[2][4];
        #pragma unroll
        for (int pc = 0; pc < 2; pc++) {
            __half2 t0 = __floats2half2_rn(s[2 * pc][0],     s[2 * pc][1]);
            __half2 t1 = __floats2half2_rn(s[2 * pc][2],     s[2 * pc][3]);
            __half2 t2 = __floats2half2_rn(s[2 * pc + 1][0], s[2 * pc + 1][1]);
            __half2 t3 = __floats2half2_rn(s[2 * pc + 1][2], s[2 * pc + 1][3]);
            pa[pc][0] = *(unsigned*)&t0; pa[pc][1] = *(unsigned*)&t1;
            pa[pc][2] = *(unsigned*)&t2; pa[pc][3] = *(unsigned*)&t3;
        }

        #pragma unroll
        for (int vn = 0; vn < 8; vn++) {
            oacc[vn][0] *= c0; oacc[vn][1] *= c0;
            oacc[vn][2] *= c1; oacc[vn][3] *= c1;
        }
        #pragma unroll
        for (int pc = 0; pc < 2; pc++) {
            #pragma unroll
            for (int vn = 0; vn < 8; vn++) {
                unsigned b0, b1;
                ldsm_x2_t(b0, b1, &Vs[st][pc * 16 + (lane & 15)][vn * 8]);
                mma16816(oacc[vn], pa[pc], b0, b1);
            }
        }
    }

    float inv0 = 1.f / l0, inv1 = 1.f / l1;
    size_t r0 = (size_t)(b * Ss + q0 + mw + gr) * Ee + h * HD_;
    size_t r1 = r0 + (size_t)8 * Ee;
    #pragma unroll
    for (int vn = 0; vn < 8; vn++) {
        int col = vn * 8 + gc * 2;
        *(__half2*)&out[r0 + col] = __floats2half2_rn(oacc[vn][0] * inv0, oacc[vn][1] * inv0);
        *(__half2*)&out[r1 + col] = __floats2half2_rn(oacc[vn][2] * inv1, oacc[vn][3] * inv1);
    }
}

// ---------------- host orchestration -----------------------------------------
extern "C" void kernel_launch(void* const* d_in, const int* in_sizes, int n_in,
                              void* d_out, int out_size) {
    const float* x      = (const float*)d_in[0];
    const int*   date   = (const int*)  d_in[1];
    const float* wpe    = (const float*)d_in[2];
    const float* ln1_w  = (const float*)d_in[3];
    const float* ln1_b  = (const float*)d_in[4];
    const float* in_w   = (const float*)d_in[5];
    const float* in_b   = (const float*)d_in[6];
    const float* out_w  = (const float*)d_in[7];
    const float* out_b  = (const float*)d_in[8];
    const float* ln2_w  = (const float*)d_in[9];
    const float* ln2_b  = (const float*)d_in[10];
    const float* fc_w   = (const float*)d_in[11];
    const float* fc_b   = (const float*)d_in[12];
    const float* proj_w = (const float*)d_in[13];
    const float* proj_b = (const float*)d_in[14];
    const float* lnf_w  = (const float*)d_in[15];
    const float* lnf_b  = (const float*)d_in[16];
    float* out = (float*)d_out;

    float  *h;
    __half *y, *qkv, *fc, *wh;
    cudaGetSymbolAddress((void**)&h,   g_h);
    cudaGetSymbolAddress((void**)&y,   g_y);
    cudaGetSymbolAddress((void**)&qkv, g_qkv);
    cudaGetSymbolAddress((void**)&fc,  g_fc);
    cudaGetSymbolAddress((void**)&wh,  g_wh);

    __half* in_wh   = wh;
    __half* out_wh  = wh + W_IN_CNT;
    __half* fc_wh   = wh + W_IN_CNT + W_OUT_CNT;
    __half* proj_wh = wh + W_IN_CNT + W_OUT_CNT + W_FC_CNT;

    // 3-stage smem: wide (WN=4) = 3*16384 + 3*32768 = 147456; narrow = 98304
    const int SMEM_WIDE = 147456, SMEM_NARROW = 98304;
    cudaFuncSetAttribute(gemm_h<4, 0>, cudaFuncAttributeMaxDynamicSharedMemorySize, SMEM_WIDE);
    cudaFuncSetAttribute(gemm_h<4, 1>, cudaFuncAttributeMaxDynamicSharedMemorySize, SMEM_WIDE);
    cudaFuncSetAttribute(gemm_h<2, 2>, cudaFuncAttributeMaxDynamicSharedMemorySize, SMEM_NARROW);

    f2h4_kernel<<<(W_IN_CNT / 4 + 255) / 256, 256>>>(in_w, in_wh, W_IN_CNT / 4);
    f2h4_kernel<<<(W_OUT_CNT / 4 + 255) / 256, 256>>>(out_w, out_wh, W_OUT_CNT / 4);
    f2h4_kernel<<<(W_FC_CNT / 4 + 255) / 256, 256>>>(fc_w, fc_wh, W_FC_CNT / 4);
    f2h4_kernel<<<(W_PROJ_CNT / 4 + 255) / 256, 256>>>(proj_w, proj_wh, W_PROJ_CNT / 4);

    embed_kernel<<<(NR * Ee + 255) / 256, 256>>>(x, date, wpe);

    for (int l = 0; l < Ll; l++) {
        ln_kernel<__half><<<NR, 256>>>(h, y, ln1_w + (size_t)l * Ee, ln1_b + (size_t)l * Ee);
        gemm_h<4, 0><<<dim3(3 * Ee / 256, NR / 128), 256, SMEM_WIDE>>>(
            y, in_wh + (size_t)l * 3 * Ee * Ee, in_b + (size_t)l * 3 * Ee, qkv,
            NR, 3 * Ee, Ee);
        attn_mma<<<dim3(Tt, Hh, Bb), 64>>>(qkv, y);
        gemm_h<2, 2><<<dim3(Ee / 128, NR / 128), 128, SMEM_NARROW>>>(
            y, out_wh + (size_t)l * Ee * Ee, out_b + (size_t)l * Ee, h,
            NR, Ee, Ee);
        ln_kernel<__half><<<NR, 256>>>(h, y, ln2_w + (size_t)l * Ee, ln2_b + (size_t)l * Ee);
        gemm_h<4, 1><<<dim3(4 * Ee / 256, NR / 128), 256, SMEM_WIDE>>>(
            y, fc_wh + (size_t)l * 4 * Ee * Ee, fc_b + (size_t)l * 4 * Ee, fc,
            NR, 4 * Ee, Ee);
        gemm_h<2, 2><<<dim3(Ee / 128, NR / 128), 128, SMEM_NARROW>>>(
            fc, proj_wh + (size_t)l * Ee * 4 * Ee, proj_b + (size_t)l * Ee, h,
            NR, Ee, 4 * Ee);
    }

    ln_kernel<float><<<NR, 256>>>(h, out, lnf_w, lnf_b);
}

// round 16
// speedup vs baseline: 1.0641x; 1.0200x over previous
#include <cuda_runtime.h>
#include <cuda_fp16.h>
#include <math.h>
#include <stdint.h>

#define Bb 8
#define Tt 32
#define Gg 32
#define Ee 768
#define Hh 12
#define Ll 4
#define Ss (Tt*Gg)        // 1024
#define HD_ (Ee/Hh)       // 64
#define NR (Bb*Ss)        // 8192 rows

// weight (half) buffer offsets
#define W_IN_CNT   (Ll*3*Ee*Ee)
#define W_OUT_CNT  (Ll*Ee*Ee)
#define W_FC_CNT   (Ll*4*Ee*Ee)
#define W_PROJ_CNT (Ll*Ee*4*Ee)

// ---------------- scratch (device globals; no cudaMalloc allowed) ------------
__device__ float  g_h[NR*Ee];             // residual stream (fp32)
__device__ __half g_y[NR*Ee];             // ln / attn output (fp16)
__device__ __half g_qkv[NR*3*Ee];         // qkv (fp16)
__device__ __half g_fc[NR*4*Ee];          // mlp hidden (fp16)
__device__ __half g_wh[W_IN_CNT + W_OUT_CNT + W_FC_CNT + W_PROJ_CNT];

// ---------------- fp32 -> fp16 weight conversion ------------------------------
__global__ void f2h4_kernel(const float* __restrict__ in, __half* __restrict__ out, int n4) {
    int i = blockIdx.x * blockDim.x + threadIdx.x;
    if (i >= n4) return;
    float4 v = ((const float4*)in)[i];
    __half2 a = __floats2half2_rn(v.x, v.y);
    __half2 b = __floats2half2_rn(v.z, v.w);
    ((__half2*)out)[i * 2]     = a;
    ((__half2*)out)[i * 2 + 1] = b;
}

// ---------------- embed -------------------------------------------------------
__global__ void embed_kernel(const float* __restrict__ x,
                             const int* __restrict__ date,
                             const float* __restrict__ wpe) {
    int idx = blockIdx.x * blockDim.x + threadIdx.x;
    if (idx >= NR * Ee) return;
    int e   = idx % Ee;
    int row = idx / Ee;
    int b   = row / Ss;
    int s   = row % Ss;
    int t   = s / Gg;
    int d   = date[b * Tt + t];
    d = min(max(d, 0), 49);
    g_h[idx] = x[idx] + wpe[d * Ee + e];
}

// ---------------- layernorm: 256 thr, single pass, shuffle reduction ----------
template<typename OT>
__global__ void __launch_bounds__(256)
ln_kernel(const float* __restrict__ in, OT* __restrict__ out,
          const float* __restrict__ w, const float* __restrict__ bia) {
    const int row = blockIdx.x;
    const int tid = threadIdx.x;
    const float* xr = in + (size_t)row * Ee;
    float x0 = xr[tid], x1 = xr[tid + 256], x2 = xr[tid + 512];
    float s = x0 + x1 + x2;
    float q = x0 * x0 + x1 * x1 + x2 * x2;
    #pragma unroll
    for (int o = 16; o > 0; o >>= 1) {
        s += __shfl_xor_sync(0xffffffffu, s, o);
        q += __shfl_xor_sync(0xffffffffu, q, o);
    }
    __shared__ float sw[8], qw[8];
    if ((tid & 31) == 0) { sw[tid >> 5] = s; qw[tid >> 5] = q; }
    __syncthreads();
    s = sw[0] + sw[1] + sw[2] + sw[3] + sw[4] + sw[5] + sw[6] + sw[7];
    q = qw[0] + qw[1] + qw[2] + qw[3] + qw[4] + qw[5] + qw[6] + qw[7];
    const float inv = 1.0f / Ee;
    float mean = s * inv;
    float var  = q * inv - mean * mean;
    float rstd = rsqrtf(var + 1e-5f);
    OT* orow = out + (size_t)row * Ee;
    orow[tid]       = (OT)((x0 - mean) * rstd * w[tid]       + bia[tid]);
    orow[tid + 256] = (OT)((x1 - mean) * rstd * w[tid + 256] + bia[tid + 256]);
    orow[tid + 512] = (OT)((x2 - mean) * rstd * w[tid + 512] + bia[tid + 512]);
}

// ---------------- cp.async helpers -------------------------------------------
__device__ __forceinline__ void cp16(void* s, const void* g) {
    unsigned sa = (unsigned)__cvta_generic_to_shared(s);
    asm volatile("cp.async.ca.shared.global [%0], [%1], 16;\n" :: "r"(sa), "l"(g));
}
__device__ __forceinline__ void cp16cg(void* s, const void* g) {
    unsigned sa = (unsigned)__cvta_generic_to_shared(s);
    asm volatile("cp.async.cg.shared.global [%0], [%1], 16;\n" :: "r"(sa), "l"(g));
}
__device__ __forceinline__ void cp_commit() {
    asm volatile("cp.async.commit_group;\n" ::);
}
template<int N>
__device__ __forceinline__ void cp_wait() {
    asm volatile("cp.async.wait_group %0;\n" :: "n"(N));
}

// ---------------- mma / ldmatrix helpers --------------------------------------
__device__ __forceinline__ void mma16816(float c[4], const unsigned a[4],
                                         unsigned b0, unsigned b1) {
    asm volatile("mma.sync.aligned.m16n8k16.row.col.f32.f16.f16.f32 "
                 "{%0,%1,%2,%3}, {%4,%5,%6,%7}, {%8,%9}, {%0,%1,%2,%3};"
                 : "+f"(c[0]), "+f"(c[1]), "+f"(c[2]), "+f"(c[3])
                 : "r"(a[0]), "r"(a[1]), "r"(a[2]), "r"(a[3]), "r"(b0), "r"(b1));
}
__device__ __forceinline__ void ldsm_x4(unsigned &r0, unsigned &r1, unsigned &r2,
                                        unsigned &r3, unsigned addr) {
    asm volatile("ldmatrix.sync.aligned.m8n8.x4.shared.b16 {%0,%1,%2,%3}, [%4];"
                 : "=r"(r0), "=r"(r1), "=r"(r2), "=r"(r3) : "r"(addr));
}
__device__ __forceinline__ void ldsm_x2_t(unsigned &r0, unsigned &r1, const void* p) {
    unsigned a = (unsigned)__cvta_generic_to_shared(p);
    asm volatile("ldmatrix.sync.aligned.m8n8.x2.trans.shared.b16 {%0,%1}, [%2];"
                 : "=r"(r0), "=r"(r1) : "r"(a));
}
// exact tanh via e^x: tanh(u) = 1 - 2/(1+exp(2u)); saturates correctly.
__device__ __forceinline__ float fast_gelu(float v) {
    float u = 0.7978845608028654f * (v + 0.044715f * v * v * v);
    float t = 1.0f - 2.0f / (1.0f + __expf(2.0f * u));
    return 0.5f * v * (1.0f + t);
}

// ---------------- fp16 HMMA GEMM, BK=64, SW128 smem, 3-stage pipeline ---------
// C[m,n] (op)= sum_k A[m,k]*W[n,k] + bias[n];  A,W fp16 K-major; fp32 acc.
// BM=128, BN=WN*64, threads=WN*64 (2 x WN warps), warp tile 64x64.
// One __syncthreads per k-tile; 2 k-tiles of cp.async in flight; .cg loads.
// EPI: 0 = store half, 1 = NewGELU -> half, 2 = add fp32 into C (residual)
template<int WN, int EPI>
__global__ void __launch_bounds__(WN * 64)
gemm_h(const __half* __restrict__ A, const __half* __restrict__ W,
       const float* __restrict__ bias, void* __restrict__ Cv,
       int M, int N, int K) {
    constexpr int BN  = WN * 64;
    constexpr int NTH = WN * 64;
    constexpr unsigned ASTAGE = 16384u;               // 128 rows * 128 B
    constexpr unsigned WOFF   = 3 * ASTAGE;           // A stages end
    constexpr unsigned WSTAGE = (unsigned)BN * 128u;
    extern __shared__ __align__(128) char sm[];
    const unsigned sb = (unsigned)__cvta_generic_to_shared(sm);

    const int m0 = blockIdx.y * 128;
    const int n0 = blockIdx.x * BN;
    const int tid  = threadIdx.x;
    const int lane = tid & 31;
    const int wid  = tid >> 5;
    const int wm = (wid & 1) * 64;
    const int wn = (wid >> 1) * 64;
    const int gr = lane >> 2;
    const int gc = lane & 3;

    const int g = lane >> 3, j = lane & 7;
    const int arowoff = ((g & 1) << 3) + j;
    const int acoff   = g >> 1;
    const int browoff = ((g >> 1) << 3) + j;
    const int bcoff   = g & 1;

    const int KT = K >> 6;

    float acc[4][8][4];
    #pragma unroll
    for (int tm = 0; tm < 4; tm++)
        #pragma unroll
        for (int tn = 0; tn < 8; tn++)
            #pragma unroll
            for (int i = 0; i < 4; i++) acc[tm][tn][i] = 0.f;

    #define LOAD_TILE(st, kt_) do {                                               \
        int k0 = (kt_) << 6;                                                      \
        _Pragma("unroll")                                                         \
        for (int i = tid; i < (128 + BN) * 8; i += NTH) {                         \
            int r = i >> 3, c = i & 7;                                            \
            if (r < 128) {                                                        \
                cp16cg(sm + (st) * ASTAGE + r * 128 + ((c ^ (r & 7)) * 16),       \
                     &A[(size_t)(m0 + r) * K + k0 + c * 8]);                      \
            } else {                                                              \
                int rr = r - 128;                                                 \
                cp16cg(sm + WOFF + (st) * WSTAGE + rr * 128 + ((c ^ (rr & 7)) * 16),\
                     &W[(size_t)(n0 + rr) * K + k0 + c * 8]);                     \
            }                                                                     \
        }                                                                         \
    } while (0)

    LOAD_TILE(0, 0); cp_commit();
    if (KT > 1) LOAD_TILE(1, 1);
    cp_commit();

    for (int kt = 0; kt < KT; kt++) {
        const int buf = kt % 3;
        cp_wait<1>();          // k-tile kt resident (kt+1 still in flight)
        __syncthreads();       // all warps finished tile kt-1 (stage (kt+2)%3 free)
        if (kt + 2 < KT) LOAD_TILE((kt + 2) % 3, kt + 2);
        cp_commit();

        const unsigned aSt = sb + buf * ASTAGE;
        const unsigned wSt = sb + WOFF + buf * WSTAGE;

        #pragma unroll
        for (int kk = 0; kk < 64; kk += 16) {
            const int cbase = kk >> 3;
            unsigned af[4][4], bf[8][2];
            #pragma unroll
            for (int tm = 0; tm < 4; tm++) {
                int row = wm + tm * 16 + arowoff;
                unsigned addr = aSt + row * 128 + (((cbase + acoff) ^ (row & 7)) << 4);
                ldsm_x4(af[tm][0], af[tm][1], af[tm][2], af[tm][3], addr);
            }
            #pragma unroll
            for (int tp = 0; tp < 4; tp++) {
                int row = wn + tp * 16 + browoff;
                unsigned addr = wSt + row * 128 + (((cbase + bcoff) ^ (row & 7)) << 4);
                ldsm_x4(bf[2 * tp][0], bf[2 * tp][1], bf[2 * tp + 1][0], bf[2 * tp + 1][1], addr);
            }
            #pragma unroll
            for (int tm = 0; tm < 4; tm++)
                #pragma unroll
                for (int tn = 0; tn < 8; tn++)
                    mma16816(acc[tm][tn], af[tm], bf[tn][0], bf[tn][1]);
        }
    }
    #undef LOAD_TILE

    #pragma unroll
    for (int tm = 0; tm < 4; tm++) {
        #pragma unroll
        for (int tn = 0; tn < 8; tn++) {
            int m = m0 + wm + tm * 16 + gr;
            int n = n0 + wn + tn * 8 + gc * 2;
            float b0 = bias[n], b1 = bias[n + 1];
            #pragma unroll
            for (int half_ = 0; half_ < 2; half_++) {
                int mm = m + half_ * 8;
                float v0 = acc[tm][tn][half_ * 2 + 0] + b0;
                float v1 = acc[tm][tn][half_ * 2 + 1] + b1;
                size_t o = (size_t)mm * N + n;
                if (EPI == 0) {
                    *(__half2*)((__half*)Cv + o) = __floats2half2_rn(v0, v1);
                } else if (EPI == 1) {
                    *(__half2*)((__half*)Cv + o) =
                        __floats2half2_rn(fast_gelu(v0), fast_gelu(v1));
                } else {
                    float* C = (float*)Cv;
                    float2 cc = *(float2*)&C[o];
                    cc.x += v0; cc.y += v1;
                    *(float2*)&C[o] = cc;
                }
            }
        }
    }
}

// ---------------- tensor-core flash attention, 64-key tiles -------------------
// One block per (b, h, 32-query T-block); 2 warps, 16 q-rows each.
// K-tiles of 64 keys; last tile half-valid when tq is even -> mask p (jn>=4).
__global__ void __launch_bounds__(64)
attn_mma(const __half* __restrict__ qkv, __half* __restrict__ out) {
    const int tq = (Tt - 1) - blockIdx.x;    // heavy tiles first
    const int h = blockIdx.y, b = blockIdx.z;
    const int q0 = tq * Gg;
    const int NT = (tq + 2) >> 1;            // 64-key tiles
    const bool last_partial = ((tq & 1) == 0);
    const int tid  = threadIdx.x;
    const int lane = tid & 31;
    const int warp = tid >> 5;
    const int gr = lane >> 2, gc = lane & 3;
    const int mw = warp * 16;

    __shared__ __half Qs[32][72];
    __shared__ __half Ks[2][64][72];
    __shared__ __half Vs[2][64][72];

    const size_t stride = 3 * Ee;
    const size_t qbase = (size_t)(b * Ss + q0) * stride + h * HD_;

    // prologue: async K/V tile 0 (64 rows; rows beyond kmax are in-bounds garbage)
    {
        size_t kb = (size_t)(b * Ss) * stride + Ee + h * HD_;
        #pragma unroll
        for (int i = 0; i < 8; i++) {
            int t = tid + i * 64; int r = t >> 3, c = (t & 7) * 8;
            cp16(&Ks[0][r][c], &qkv[kb + (size_t)r * stride + c]);
            cp16(&Vs[0][r][c], &qkv[kb + Ee + (size_t)r * stride + c]);
        }
        cp_commit();
    }
    // Q tile [32 x 64] direct
    #pragma unroll
    for (int i = 0; i < 4; i++) {
        int t = tid + i * 64; int r = t >> 3, c = (t & 7) * 8;
        *(uint4*)&Qs[r][c] = *(const uint4*)&qkv[qbase + (size_t)r * stride + c];
    }
    __syncthreads();

    unsigned qa[4][4];
    #pragma unroll
    for (int kc = 0; kc < 4; kc++) {
        qa[kc][0] = *(const unsigned*)&Qs[mw + gr][kc * 16 + gc * 2];
        qa[kc][1] = *(const unsigned*)&Qs[mw + gr + 8][kc * 16 + gc * 2];
        qa[kc][2] = *(const unsigned*)&Qs[mw + gr][kc * 16 + gc * 2 + 8];
        qa[kc][3] = *(const unsigned*)&Qs[mw + gr + 8][kc * 16 + gc * 2 + 8];
    }

    float m0r = -1e30f, m1r = -1e30f, l0 = 0.f, l1 = 0.f;
    float oacc[8][4];
    #pragma unroll
    for (int vn = 0; vn < 8; vn++)
        #pragma unroll
        for (int c = 0; c < 4; c++) oacc[vn][c] = 0.f;

    for (int kt = 0; kt < NT; kt++) {
        const int st = kt & 1;
        cp_wait<0>();
        __syncthreads();
        if (kt + 1 < NT) {
            size_t kb = (size_t)(b * Ss + (kt + 1) * 64) * stride + Ee + h * HD_;
            #pragma unroll
            for (int i = 0; i < 8; i++) {
                int t = tid + i * 64; int r = t >> 3, c = (t & 7) * 8;
                cp16(&Ks[st ^ 1][r][c], &qkv[kb + (size_t)r * stride + c]);
                cp16(&Vs[st ^ 1][r][c], &qkv[kb + Ee + (size_t)r * stride + c]);
            }
            cp_commit();
        }
        const bool full = !(last_partial && kt == NT - 1);

        // ---- S = Q @ K^T  (16 x 64 per warp) ----
        float s[8][4];
        #pragma unroll
        for (int jn = 0; jn < 8; jn++)
            s[jn][0] = s[jn][1] = s[jn][2] = s[jn][3] = 0.f;
        #pragma unroll
        for (int kc = 0; kc < 4; kc++) {
            #pragma unroll
            for (int jn = 0; jn < 8; jn++) {
                unsigned b0 = *(const unsigned*)&Ks[st][jn * 8 + gr][kc * 16 + gc * 2];
                unsigned b1 = *(const unsigned*)&Ks[st][jn * 8 + gr][kc * 16 + gc * 2 + 8];
                mma16816(s[jn], qa[kc], b0, b1);
            }
        }

        // ---- online softmax (garbage keys allowed in max; masked after exp) ----
        float mt0 = -1e30f, mt1 = -1e30f;
        #pragma unroll
        for (int jn = 0; jn < 8; jn++) {
            s[jn][0] *= 0.125f; s[jn][1] *= 0.125f;
            s[jn][2] *= 0.125f; s[jn][3] *= 0.125f;
            mt0 = fmaxf(mt0, fmaxf(s[jn][0], s[jn][1]));
            mt1 = fmaxf(mt1, fmaxf(s[jn][2], s[jn][3]));
        }
        mt0 = fmaxf(mt0, __shfl_xor_sync(0xffffffffu, mt0, 1));
        mt0 = fmaxf(mt0, __shfl_xor_sync(0xffffffffu, mt0, 2));
        mt1 = fmaxf(mt1, __shfl_xor_sync(0xffffffffu, mt1, 1));
        mt1 = fmaxf(mt1, __shfl_xor_sync(0xffffffffu, mt1, 2));
        float mn0 = fmaxf(m0r, mt0), mn1 = fmaxf(m1r, mt1);
        float c0 = __expf(m0r - mn0), c1 = __expf(m1r - mn1);
        m0r = mn0; m1r = mn1;
        float rs0 = 0.f, rs1 = 0.f;
        #pragma unroll
        for (int jn = 0; jn < 8; jn++) {
            float msk = (full || jn < 4) ? 1.f : 0.f;
            s[jn][0] = __expf(s[jn][0] - mn0) * msk;
            s[jn][1] = __expf(s[jn][1] - mn0) * msk;
            s[jn][2] = __expf(s[jn][2] - mn1) * msk;
            s[jn][3] = __expf(s[jn][3] - mn1) * msk;
            rs0 += s[jn][0] + s[jn][1];
            rs1 += s[jn][2] + s[jn][3];
        }
        rs0 += __shfl_xor_sync(0xffffffffu, rs0, 1);
        rs0 += __shfl_xor_sync(0xffffffffu, rs0, 2);
        rs1 += __shfl_xor_sync(0xffffffffu, rs1, 1);
        rs1 += __shfl_xor_sync(0xffffffffu, rs1, 2);
        l0 = l0 * c0 + rs0;
        l1 = l1 * c1 + rs1;

        // ---- P (C-layout) -> fp16 A-fragments (4 chunks of k=16) ----
        unsigned pa[4][4];
        #pragma unroll
        for (int pc = 0; pc < 4; pc++) {
            __half2 t0 = __floats2half2_rn(s[2 * pc][0],     s[2 * pc][1]);
            __half2 t1 = __floats2half2_rn(s[2 * pc][2],     s[2 * pc][3]);
            __half2 t2 = __floats2half2_rn(s[2 * pc + 1][0], s[2 * pc + 1][1]);
            __half2 t3 = __floats2half2_rn(s[2 * pc + 1][2], s[2 * pc + 1][3]);
            pa[pc][0] = *(unsigned*)&t0; pa[pc][1] = *(unsigned*)&t1;
            pa[pc][2] = *(unsigned*)&t2; pa[pc][3] = *(unsigned*)&t3;
        }

        // ---- O = O*corr + P @ V ----
        #pragma unroll
        for (int vn = 0; vn < 8; vn++) {
            oacc[vn][0] *= c0; oacc[vn][1] *= c0;
            oacc[vn][2] *= c1; oacc[vn][3] *= c1;
        }
        #pragma unroll
        for (int pc = 0; pc < 4; pc++) {
            #pragma unroll
            for (int vn = 0; vn < 8; vn++) {
                unsigned b0, b1;
                ldsm_x2_t(b0, b1, &Vs[st][pc * 16 + (lane & 15)][vn * 8]);
                mma16816(oacc[vn], pa[pc], b0, b1);
            }
        }
    }

    float inv0 = 1.f / l0, inv1 = 1.f / l1;
    size_t r0 = (size_t)(b * Ss + q0 + mw + gr) * Ee + h * HD_;
    size_t r1 = r0 + (size_t)8 * Ee;
    #pragma unroll
    for (int vn = 0; vn < 8; vn++) {
        int col = vn * 8 + gc * 2;
        *(__half2*)&out[r0 + col] = __floats2half2_rn(oacc[vn][0] * inv0, oacc[vn][1] * inv0);
        *(__half2*)&out[r1 + col] = __floats2half2_rn(oacc[vn][2] * inv1, oacc[vn][3] * inv1);
    }
}

// ---------------- host orchestration -----------------------------------------
extern "C" void kernel_launch(void* const* d_in, const int* in_sizes, int n_in,
                              void* d_out, int out_size) {
    const float* x      = (const float*)d_in[0];
    const int*   date   = (const int*)  d_in[1];
    const float* wpe    = (const float*)d_in[2];
    const float* ln1_w  = (const float*)d_in[3];
    const float* ln1_b  = (const float*)d_in[4];
    const float* in_w   = (const float*)d_in[5];
    const float* in_b   = (const float*)d_in[6];
    const float* out_w  = (const float*)d_in[7];
    const float* out_b  = (const float*)d_in[8];
    const float* ln2_w  = (const float*)d_in[9];
    const float* ln2_b  = (const float*)d_in[10];
    const float* fc_w   = (const float*)d_in[11];
    const float* fc_b   = (const float*)d_in[12];
    const float* proj_w = (const float*)d_in[13];
    const float* proj_b = (const float*)d_in[14];
    const float* lnf_w  = (const float*)d_in[15];
    const float* lnf_b  = (const float*)d_in[16];
    float* out = (float*)d_out;

    float  *h;
    __half *y, *qkv, *fc, *wh;
    cudaGetSymbolAddress((void**)&h,   g_h);
    cudaGetSymbolAddress((void**)&y,   g_y);
    cudaGetSymbolAddress((void**)&qkv, g_qkv);
    cudaGetSymbolAddress((void**)&fc,  g_fc);
    cudaGetSymbolAddress((void**)&wh,  g_wh);

    __half* in_wh   = wh;
    __half* out_wh  = wh + W_IN_CNT;
    __half* fc_wh   = wh + W_IN_CNT + W_OUT_CNT;
    __half* proj_wh = wh + W_IN_CNT + W_OUT_CNT + W_FC_CNT;

    // 3-stage smem: wide (WN=4) = 3*16384 + 3*32768 = 147456; narrow = 98304
    const int SMEM_WIDE = 147456, SMEM_NARROW = 98304;
    cudaFuncSetAttribute(gemm_h<4, 0>, cudaFuncAttributeMaxDynamicSharedMemorySize, SMEM_WIDE);
    cudaFuncSetAttribute(gemm_h<4, 1>, cudaFuncAttributeMaxDynamicSharedMemorySize, SMEM_WIDE);
    cudaFuncSetAttribute(gemm_h<2, 2>, cudaFuncAttributeMaxDynamicSharedMemorySize, SMEM_NARROW);

    f2h4_kernel<<<(W_IN_CNT / 4 + 255) / 256, 256>>>(in_w, in_wh, W_IN_CNT / 4);
    f2h4_kernel<<<(W_OUT_CNT / 4 + 255) / 256, 256>>>(out_w, out_wh, W_OUT_CNT / 4);
    f2h4_kernel<<<(W_FC_CNT / 4 + 255) / 256, 256>>>(fc_w, fc_wh, W_FC_CNT / 4);
    f2h4_kernel<<<(W_PROJ_CNT / 4 + 255) / 256, 256>>>(proj_w, proj_wh, W_PROJ_CNT / 4);

    embed_kernel<<<(NR * Ee + 255) / 256, 256>>>(x, date, wpe);

    for (int l = 0; l < Ll; l++) {
        ln_kernel<__half><<<NR, 256>>>(h, y, ln1_w + (size_t)l * Ee, ln1_b + (size_t)l * Ee);
        gemm_h<4, 0><<<dim3(3 * Ee / 256, NR / 128), 256, SMEM_WIDE>>>(
            y, in_wh + (size_t)l * 3 * Ee * Ee, in_b + (size_t)l * 3 * Ee, qkv,
            NR, 3 * Ee, Ee);
        attn_mma<<<dim3(Tt, Hh, Bb), 64>>>(qkv, y);
        gemm_h<2, 2><<<dim3(Ee / 128, NR / 128), 128, SMEM_NARROW>>>(
            y, out_wh + (size_t)l * Ee * Ee, out_b + (size_t)l * Ee, h,
            NR, Ee, Ee);
        ln_kernel<__half><<<NR, 256>>>(h, y, ln2_w + (size_t)l * Ee, ln2_b + (size_t)l * Ee);
        gemm_h<4, 1><<<dim3(4 * Ee / 256, NR / 128), 256, SMEM_WIDE>>>(
            y, fc_wh + (size_t)l * 4 * Ee * Ee, fc_b + (size_t)l * 4 * Ee, fc,
            NR, 4 * Ee, Ee);
        gemm_h<2, 2><<<dim3(Ee / 128, NR / 128), 128, SMEM_NARROW>>>(
            fc, proj_wh + (size_t)l * Ee * 4 * Ee, proj_b + (size_t)l * Ee, h,
            NR, Ee, 4 * Ee);
    }

    ln_kernel<float><<<NR, 256>>>(h, out, lnf_w, lnf_b);
}

// round 17
// speedup vs baseline: 1.0728x; 1.0082x over previous
#include <cuda_runtime.h>
#include <cuda_fp16.h>
#include <math.h>
#include <stdint.h>

#define Bb 8
#define Tt 32
#define Gg 32
#define Ee 768
#define Hh 12
#define Ll 4
#define Ss (Tt*Gg)        // 1024
#define HD_ (Ee/Hh)       // 64
#define NR (Bb*Ss)        // 8192 rows

// weight (half) buffer offsets
#define W_IN_CNT   (Ll*3*Ee*Ee)
#define W_OUT_CNT  (Ll*Ee*Ee)
#define W_FC_CNT   (Ll*4*Ee*Ee)
#define W_PROJ_CNT (Ll*Ee*4*Ee)

// ---------------- scratch (device globals; no cudaMalloc allowed) ------------
__device__ float  g_h[NR*Ee];             // residual stream (fp32)
__device__ __half g_y[NR*Ee];             // ln / attn output (fp16)
__device__ __half g_qkv[NR*3*Ee];         // qkv (fp16)
__device__ __half g_fc[NR*4*Ee];          // mlp hidden (fp16)
__device__ __half g_wh[W_IN_CNT + W_OUT_CNT + W_FC_CNT + W_PROJ_CNT];

// ---------------- fp32 -> fp16 weight conversion (all 4 groups, 1 launch) -----
__global__ void f2h_all_kernel(const float* __restrict__ in0, const float* __restrict__ in1,
                               const float* __restrict__ in2, const float* __restrict__ in3,
                               __half* __restrict__ out) {
    const int c0 = W_IN_CNT / 4, c1 = W_OUT_CNT / 4, c2 = W_FC_CNT / 4, c3 = W_PROJ_CNT / 4;
    int i = blockIdx.x * blockDim.x + threadIdx.x;
    if (i >= c0 + c1 + c2 + c3) return;
    const float* src; int o;
    if (i < c0)               { src = in0; o = i; }
    else if (i < c0 + c1)     { src = in1; o = i - c0; }
    else if (i < c0 + c1 + c2){ src = in2; o = i - c0 - c1; }
    else                      { src = in3; o = i - c0 - c1 - c2; }
    float4 v = ((const float4*)src)[o];
    __half2 a = __floats2half2_rn(v.x, v.y);
    __half2 b = __floats2half2_rn(v.z, v.w);
    ((__half2*)out)[i * 2]     = a;
    ((__half2*)out)[i * 2 + 1] = b;
}

// ---------------- fused embed + LN1(layer0): h = x+pos; y = LN(h) -------------
__global__ void __launch_bounds__(256)
embed_ln_kernel(const float* __restrict__ x, const int* __restrict__ date,
                const float* __restrict__ wpe,
                float* __restrict__ hout, __half* __restrict__ yout,
                const float* __restrict__ w, const float* __restrict__ bia) {
    const int row = blockIdx.x;         // b*S + s
    const int tid = threadIdx.x;
    const int b = row / Ss, s = row % Ss, t = s / Gg;
    int d = date[b * Tt + t];
    d = min(max(d, 0), 49);
    const float* xr = x + (size_t)row * Ee;
    const float* pr = wpe + (size_t)d * Ee;
    float x0 = xr[tid]       + pr[tid];
    float x1 = xr[tid + 256] + pr[tid + 256];
    float x2 = xr[tid + 512] + pr[tid + 512];
    float* hr = hout + (size_t)row * Ee;
    hr[tid] = x0; hr[tid + 256] = x1; hr[tid + 512] = x2;
    float sacc = x0 + x1 + x2;
    float qacc = x0 * x0 + x1 * x1 + x2 * x2;
    #pragma unroll
    for (int o = 16; o > 0; o >>= 1) {
        sacc += __shfl_xor_sync(0xffffffffu, sacc, o);
        qacc += __shfl_xor_sync(0xffffffffu, qacc, o);
    }
    __shared__ float sw[8], qw[8];
    if ((tid & 31) == 0) { sw[tid >> 5] = sacc; qw[tid >> 5] = qacc; }
    __syncthreads();
    sacc = sw[0] + sw[1] + sw[2] + sw[3] + sw[4] + sw[5] + sw[6] + sw[7];
    qacc = qw[0] + qw[1] + qw[2] + qw[3] + qw[4] + qw[5] + qw[6] + qw[7];
    const float inv = 1.0f / Ee;
    float mean = sacc * inv;
    float var  = qacc * inv - mean * mean;
    float rstd = rsqrtf(var + 1e-5f);
    __half* yr = yout + (size_t)row * Ee;
    yr[tid]       = (__half)((x0 - mean) * rstd * w[tid]       + bia[tid]);
    yr[tid + 256] = (__half)((x1 - mean) * rstd * w[tid + 256] + bia[tid + 256]);
    yr[tid + 512] = (__half)((x2 - mean) * rstd * w[tid + 512] + bia[tid + 512]);
}

// ---------------- layernorm: 256 thr, single pass, shuffle reduction ----------
template<typename OT>
__global__ void __launch_bounds__(256)
ln_kernel(const float* __restrict__ in, OT* __restrict__ out,
          const float* __restrict__ w, const float* __restrict__ bia) {
    const int row = blockIdx.x;
    const int tid = threadIdx.x;
    const float* xr = in + (size_t)row * Ee;
    float x0 = xr[tid], x1 = xr[tid + 256], x2 = xr[tid + 512];
    float s = x0 + x1 + x2;
    float q = x0 * x0 + x1 * x1 + x2 * x2;
    #pragma unroll
    for (int o = 16; o > 0; o >>= 1) {
        s += __shfl_xor_sync(0xffffffffu, s, o);
        q += __shfl_xor_sync(0xffffffffu, q, o);
    }
    __shared__ float sw[8], qw[8];
    if ((tid & 31) == 0) { sw[tid >> 5] = s; qw[tid >> 5] = q; }
    __syncthreads();
    s = sw[0] + sw[1] + sw[2] + sw[3] + sw[4] + sw[5] + sw[6] + sw[7];
    q = qw[0] + qw[1] + qw[2] + qw[3] + qw[4] + qw[5] + qw[6] + qw[7];
    const float inv = 1.0f / Ee;
    float mean = s * inv;
    float var  = q * inv - mean * mean;
    float rstd = rsqrtf(var + 1e-5f);
    OT* orow = out + (size_t)row * Ee;
    orow[tid]       = (OT)((x0 - mean) * rstd * w[tid]       + bia[tid]);
    orow[tid + 256] = (OT)((x1 - mean) * rstd * w[tid + 256] + bia[tid + 256]);
    orow[tid + 512] = (OT)((x2 - mean) * rstd * w[tid + 512] + bia[tid + 512]);
}

// ---------------- cp.async helpers -------------------------------------------
__device__ __forceinline__ void cp16(void* s, const void* g) {
    unsigned sa = (unsigned)__cvta_generic_to_shared(s);
    asm volatile("cp.async.ca.shared.global [%0], [%1], 16;\n" :: "r"(sa), "l"(g));
}
__device__ __forceinline__ void cp16cg(void* s, const void* g) {
    unsigned sa = (unsigned)__cvta_generic_to_shared(s);
    asm volatile("cp.async.cg.shared.global [%0], [%1], 16;\n" :: "r"(sa), "l"(g));
}
__device__ __forceinline__ void cp_commit() {
    asm volatile("cp.async.commit_group;\n" ::);
}
template<int N>
__device__ __forceinline__ void cp_wait() {
    asm volatile("cp.async.wait_group %0;\n" :: "n"(N));
}

// ---------------- mma / ldmatrix helpers --------------------------------------
__device__ __forceinline__ void mma16816(float c[4], const unsigned a[4],
                                         unsigned b0, unsigned b1) {
    asm volatile("mma.sync.aligned.m16n8k16.row.col.f32.f16.f16.f32 "
                 "{%0,%1,%2,%3}, {%4,%5,%6,%7}, {%8,%9}, {%0,%1,%2,%3};"
                 : "+f"(c[0]), "+f"(c[1]), "+f"(c[2]), "+f"(c[3])
                 : "r"(a[0]), "r"(a[1]), "r"(a[2]), "r"(a[3]), "r"(b0), "r"(b1));
}
__device__ __forceinline__ void ldsm_x4(unsigned &r0, unsigned &r1, unsigned &r2,
                                        unsigned &r3, unsigned addr) {
    asm volatile("ldmatrix.sync.aligned.m8n8.x4.shared.b16 {%0,%1,%2,%3}, [%4];"
                 : "=r"(r0), "=r"(r1), "=r"(r2), "=r"(r3) : "r"(addr));
}
__device__ __forceinline__ void ldsm_x2_t(unsigned &r0, unsigned &r1, const void* p) {
    unsigned a = (unsigned)__cvta_generic_to_shared(p);
    asm volatile("ldmatrix.sync.aligned.m8n8.x2.trans.shared.b16 {%0,%1}, [%2];"
                 : "=r"(r0), "=r"(r1) : "r"(a));
}
// exact tanh via e^x: tanh(u) = 1 - 2/(1+exp(2u)); saturates correctly.
__device__ __forceinline__ float fast_gelu(float v) {
    float u = 0.7978845608028654f * (v + 0.044715f * v * v * v);
    float t = 1.0f - 2.0f / (1.0f + __expf(2.0f * u));
    return 0.5f * v * (1.0f + t);
}

// ---------------- fp16 HMMA GEMM, BK=64, SW128 smem, 3-stage pipeline ---------
// C[m,n] (op)= sum_k A[m,k]*W[n,k] + bias[n];  A,W fp16 K-major; fp32 acc.
// BM=128, BN=WN*64, threads=WN*64 (2 x WN warps), warp tile 64x64.
// One __syncthreads per k-tile; 2 k-tiles of cp.async in flight; .cg loads.
// EPI: 0 = store half, 1 = NewGELU -> half, 2 = add fp32 into C (residual)
template<int WN, int EPI>
__global__ void __launch_bounds__(WN * 64)
gemm_h(const __half* __restrict__ A, const __half* __restrict__ W,
       const float* __restrict__ bias, void* __restrict__ Cv,
       int M, int N, int K) {
    constexpr int BN  = WN * 64;
    constexpr int NTH = WN * 64;
    constexpr unsigned ASTAGE = 16384u;               // 128 rows * 128 B
    constexpr unsigned WOFF   = 3 * ASTAGE;           // A stages end
    constexpr unsigned WSTAGE = (unsigned)BN * 128u;
    extern __shared__ __align__(128) char sm[];
    const unsigned sb = (unsigned)__cvta_generic_to_shared(sm);

    const int m0 = blockIdx.y * 128;
    const int n0 = blockIdx.x * BN;
    const int tid  = threadIdx.x;
    const int lane = tid & 31;
    const int wid  = tid >> 5;
    const int wm = (wid & 1) * 64;
    const int wn = (wid >> 1) * 64;
    const int gr = lane >> 2;
    const int gc = lane & 3;

    const int g = lane >> 3, j = lane & 7;
    const int arowoff = ((g & 1) << 3) + j;
    const int acoff   = g >> 1;
    const int browoff = ((g >> 1) << 3) + j;
    const int bcoff   = g & 1;

    const int KT = K >> 6;

    float acc[4][8][4];
    #pragma unroll
    for (int tm = 0; tm < 4; tm++)
        #pragma unroll
        for (int tn = 0; tn < 8; tn++)
            #pragma unroll
            for (int i = 0; i < 4; i++) acc[tm][tn][i] = 0.f;

    #define LOAD_TILE(st, kt_) do {                                               \
        int k0 = (kt_) << 6;                                                      \
        _Pragma("unroll")                                                         \
        for (int i = tid; i < (128 + BN) * 8; i += NTH) {                         \
            int r = i >> 3, c = i & 7;                                            \
            if (r < 128) {                                                        \
                cp16cg(sm + (st) * ASTAGE + r * 128 + ((c ^ (r & 7)) * 16),       \
                     &A[(size_t)(m0 + r) * K + k0 + c * 8]);                      \
            } else {                                                              \
                int rr = r - 128;                                                 \
                cp16cg(sm + WOFF + (st) * WSTAGE + rr * 128 + ((c ^ (rr & 7)) * 16),\
                     &W[(size_t)(n0 + rr) * K + k0 + c * 8]);                     \
            }                                                                     \
        }                                                                         \
    } while (0)

    LOAD_TILE(0, 0); cp_commit();
    if (KT > 1) LOAD_TILE(1, 1);
    cp_commit();

    for (int kt = 0; kt < KT; kt++) {
        const int buf = kt % 3;
        cp_wait<1>();          // k-tile kt resident (kt+1 still in flight)
        __syncthreads();       // all warps finished tile kt-1 (stage (kt+2)%3 free)
        if (kt + 2 < KT) LOAD_TILE((kt + 2) % 3, kt + 2);
        cp_commit();

        const unsigned aSt = sb + buf * ASTAGE;
        const unsigned wSt = sb + WOFF + buf * WSTAGE;

        #pragma unroll
        for (int kk = 0; kk < 64; kk += 16) {
            const int cbase = kk >> 3;
            unsigned af[4][4], bf[8][2];
            #pragma unroll
            for (int tm = 0; tm < 4; tm++) {
                int row = wm + tm * 16 + arowoff;
                unsigned addr = aSt + row * 128 + (((cbase + acoff) ^ (row & 7)) << 4);
                ldsm_x4(af[tm][0], af[tm][1], af[tm][2], af[tm][3], addr);
            }
            #pragma unroll
            for (int tp = 0; tp < 4; tp++) {
                int row = wn + tp * 16 + browoff;
                unsigned addr = wSt + row * 128 + (((cbase + bcoff) ^ (row & 7)) << 4);
                ldsm_x4(bf[2 * tp][0], bf[2 * tp][1], bf[2 * tp + 1][0], bf[2 * tp + 1][1], addr);
            }
            #pragma unroll
            for (int tm = 0; tm < 4; tm++)
                #pragma unroll
                for (int tn = 0; tn < 8; tn++)
                    mma16816(acc[tm][tn], af[tm], bf[tn][0], bf[tn][1]);
        }
    }
    #undef LOAD_TILE

    #pragma unroll
    for (int tm = 0; tm < 4; tm++) {
        #pragma unroll
        for (int tn = 0; tn < 8; tn++) {
            int m = m0 + wm + tm * 16 + gr;
            int n = n0 + wn + tn * 8 + gc * 2;
            float b0 = bias[n], b1 = bias[n + 1];
            #pragma unroll
            for (int half_ = 0; half_ < 2; half_++) {
                int mm = m + half_ * 8;
                float v0 = acc[tm][tn][half_ * 2 + 0] + b0;
                float v1 = acc[tm][tn][half_ * 2 + 1] + b1;
                size_t o = (size_t)mm * N + n;
                if (EPI == 0) {
                    *(__half2*)((__half*)Cv + o) = __floats2half2_rn(v0, v1);
                } else if (EPI == 1) {
                    *(__half2*)((__half*)Cv + o) =
                        __floats2half2_rn(fast_gelu(v0), fast_gelu(v1));
                } else {
                    float* C = (float*)Cv;
                    float2 cc = *(float2*)&C[o];
                    cc.x += v0; cc.y += v1;
                    *(float2*)&C[o] = cc;
                }
            }
        }
    }
}

// ---------------- tensor-core flash attention, 64-key tiles -------------------
// One block per (b, h, 32-query T-block); 2 warps, 16 q-rows each.
// K-tiles of 64 keys; last tile half-valid when tq is even -> mask p (jn>=4).
__global__ void __launch_bounds__(64)
attn_mma(const __half* __restrict__ qkv, __half* __restrict__ out) {
    const int tq = (Tt - 1) - blockIdx.x;    // heavy tiles first
    const int h = blockIdx.y, b = blockIdx.z;
    const int q0 = tq * Gg;
    const int NT = (tq + 2) >> 1;            // 64-key tiles
    const bool last_partial = ((tq & 1) == 0);
    const int tid  = threadIdx.x;
    const int lane = tid & 31;
    const int warp = tid >> 5;
    const int gr = lane >> 2, gc = lane & 3;
    const int mw = warp * 16;

    __shared__ __half Qs[32][72];
    __shared__ __half Ks[2][64][72];
    __shared__ __half Vs[2][64][72];

    const size_t stride = 3 * Ee;
    const size_t qbase = (size_t)(b * Ss + q0) * stride + h * HD_;

    // prologue: async K/V tile 0 (64 rows; rows beyond kmax are in-bounds garbage)
    {
        size_t kb = (size_t)(b * Ss) * stride + Ee + h * HD_;
        #pragma unroll
        for (int i = 0; i < 8; i++) {
            int t = tid + i * 64; int r = t >> 3, c = (t & 7) * 8;
            cp16(&Ks[0][r][c], &qkv[kb + (size_t)r * stride + c]);
            cp16(&Vs[0][r][c], &qkv[kb + Ee + (size_t)r * stride + c]);
        }
        cp_commit();
    }
    // Q tile [32 x 64] direct
    #pragma unroll
    for (int i = 0; i < 4; i++) {
        int t = tid + i * 64; int r = t >> 3, c = (t & 7) * 8;
        *(uint4*)&Qs[r][c] = *(const uint4*)&qkv[qbase + (size_t)r * stride + c];
    }
    __syncthreads();

    unsigned qa[4][4];
    #pragma unroll
    for (int kc = 0; kc < 4; kc++) {
        qa[kc][0] = *(const unsigned*)&Qs[mw + gr][kc * 16 + gc * 2];
        qa[kc][1] = *(const unsigned*)&Qs[mw + gr + 8][kc * 16 + gc * 2];
        qa[kc][2] = *(const unsigned*)&Qs[mw + gr][kc * 16 + gc * 2 + 8];
        qa[kc][3] = *(const unsigned*)&Qs[mw + gr + 8][kc * 16 + gc * 2 + 8];
    }

    float m0r = -1e30f, m1r = -1e30f, l0 = 0.f, l1 = 0.f;
    float oacc[8][4];
    #pragma unroll
    for (int vn = 0; vn < 8; vn++)
        #pragma unroll
        for (int c = 0; c < 4; c++) oacc[vn][c] = 0.f;

    for (int kt = 0; kt < NT; kt++) {
        const int st = kt & 1;
        cp_wait<0>();
        __syncthreads();
        if (kt + 1 < NT) {
            size_t kb = (size_t)(b * Ss + (kt + 1) * 64) * stride + Ee + h * HD_;
            #pragma unroll
            for (int i = 0; i < 8; i++) {
                int t = tid + i * 64; int r = t >> 3, c = (t & 7) * 8;
                cp16(&Ks[st ^ 1][r][c], &qkv[kb + (size_t)r * stride + c]);
                cp16(&Vs[st ^ 1][r][c], &qkv[kb + Ee + (size_t)r * stride + c]);
            }
            cp_commit();
        }
        const bool full = !(last_partial && kt == NT - 1);

        // ---- S = Q @ K^T  (16 x 64 per warp) ----
        float s[8][4];
        #pragma unroll
        for (int jn = 0; jn < 8; jn++)
            s[jn][0] = s[jn][1] = s[jn][2] = s[jn][3] = 0.f;
        #pragma unroll
        for (int kc = 0; kc < 4; kc++) {
            #pragma unroll
            for (int jn = 0; jn < 8; jn++) {
                unsigned b0 = *(const unsigned*)&Ks[st][jn * 8 + gr][kc * 16 + gc * 2];
                unsigned b1 = *(const unsigned*)&Ks[st][jn * 8 + gr][kc * 16 + gc * 2 + 8];
                mma16816(s[jn], qa[kc], b0, b1);
            }
        }

        // ---- online softmax (garbage keys allowed in max; masked after exp) ----
        float mt0 = -1e30f, mt1 = -1e30f;
        #pragma unroll
        for (int jn = 0; jn < 8; jn++) {
            s[jn][0] *= 0.125f; s[jn][1] *= 0.125f;
            s[jn][2] *= 0.125f; s[jn][3] *= 0.125f;
            mt0 = fmaxf(mt0, fmaxf(s[jn][0], s[jn][1]));
            mt1 = fmaxf(mt1, fmaxf(s[jn][2], s[jn][3]));
        }
        mt0 = fmaxf(mt0, __shfl_xor_sync(0xffffffffu, mt0, 1));
        mt0 = fmaxf(mt0, __shfl_xor_sync(0xffffffffu, mt0, 2));
        mt1 = fmaxf(mt1, __shfl_xor_sync(0xffffffffu, mt1, 1));
        mt1 = fmaxf(mt1, __shfl_xor_sync(0xffffffffu, mt1, 2));
        float mn0 = fmaxf(m0r, mt0), mn1 = fmaxf(m1r, mt1);
        float c0 = __expf(m0r - mn0), c1 = __expf(m1r - mn1);
        m0r = mn0; m1r = mn1;
        float rs0 = 0.f, rs1 = 0.f;
        #pragma unroll
        for (int jn = 0; jn < 8; jn++) {
            float msk = (full || jn < 4) ? 1.f : 0.f;
            s[jn][0] = __expf(s[jn][0] - mn0) * msk;
            s[jn][1] = __expf(s[jn][1] - mn0) * msk;
            s[jn][2] = __expf(s[jn][2] - mn1) * msk;
            s[jn][3] = __expf(s[jn][3] - mn1) * msk;
            rs0 += s[jn][0] + s[jn][1];
            rs1 += s[jn][2] + s[jn][3];
        }
        rs0 += __shfl_xor_sync(0xffffffffu, rs0, 1);
        rs0 += __shfl_xor_sync(0xffffffffu, rs0, 2);
        rs1 += __shfl_xor_sync(0xffffffffu, rs1, 1);
        rs1 += __shfl_xor_sync(0xffffffffu, rs1, 2);
        l0 = l0 * c0 + rs0;
        l1 = l1 * c1 + rs1;

        // ---- P (C-layout) -> fp16 A-fragments (4 chunks of k=16) ----
        unsigned pa[4][4];
        #pragma unroll
        for (int pc = 0; pc < 4; pc++) {
            __half2 t0 = __floats2half2_rn(s[2 * pc][0],     s[2 * pc][1]);
            __half2 t1 = __floats2half2_rn(s[2 * pc][2],     s[2 * pc][3]);
            __half2 t2 = __floats2half2_rn(s[2 * pc + 1][0], s[2 * pc + 1][1]);
            __half2 t3 = __floats2half2_rn(s[2 * pc + 1][2], s[2 * pc + 1][3]);
            pa[pc][0] = *(unsigned*)&t0; pa[pc][1] = *(unsigned*)&t1;
            pa[pc][2] = *(unsigned*)&t2; pa[pc][3] = *(unsigned*)&t3;
        }

        // ---- O = O*corr + P @ V ----
        #pragma unroll
        for (int vn = 0; vn < 8; vn++) {
            oacc[vn][0] *= c0; oacc[vn][1] *= c0;
            oacc[vn][2] *= c1; oacc[vn][3] *= c1;
        }
        #pragma unroll
        for (int pc = 0; pc < 4; pc++) {
            #pragma unroll
            for (int vn = 0; vn < 8; vn++) {
                unsigned b0, b1;
                ldsm_x2_t(b0, b1, &Vs[st][pc * 16 + (lane & 15)][vn * 8]);
                mma16816(oacc[vn], pa[pc], b0, b1);
            }
        }
    }

    float inv0 = 1.f / l0, inv1 = 1.f / l1;
    size_t r0 = (size_t)(b * Ss + q0 + mw + gr) * Ee + h * HD_;
    size_t r1 = r0 + (size_t)8 * Ee;
    #pragma unroll
    for (int vn = 0; vn < 8; vn++) {
        int col = vn * 8 + gc * 2;
        *(__half2*)&out[r0 + col] = __floats2half2_rn(oacc[vn][0] * inv0, oacc[vn][1] * inv0);
        *(__half2*)&out[r1 + col] = __floats2half2_rn(oacc[vn][2] * inv1, oacc[vn][3] * inv1);
    }
}

// ---------------- host orchestration -----------------------------------------
extern "C" void kernel_launch(void* const* d_in, const int* in_sizes, int n_in,
                              void* d_out, int out_size) {
    const float* x      = (const float*)d_in[0];
    const int*   date   = (const int*)  d_in[1];
    const float* wpe    = (const float*)d_in[2];
    const float* ln1_w  = (const float*)d_in[3];
    const float* ln1_b  = (const float*)d_in[4];
    const float* in_w   = (const float*)d_in[5];
    const float* in_b   = (const float*)d_in[6];
    const float* out_w  = (const float*)d_in[7];
    const float* out_b  = (const float*)d_in[8];
    const float* ln2_w  = (const float*)d_in[9];
    const float* ln2_b  = (const float*)d_in[10];
    const float* fc_w   = (const float*)d_in[11];
    const float* fc_b   = (const float*)d_in[12];
    const float* proj_w = (const float*)d_in[13];
    const float* proj_b = (const float*)d_in[14];
    const float* lnf_w  = (const float*)d_in[15];
    const float* lnf_b  = (const float*)d_in[16];
    float* out = (float*)d_out;

    float  *h;
    __half *y, *qkv, *fc, *wh;
    cudaGetSymbolAddress((void**)&h,   g_h);
    cudaGetSymbolAddress((void**)&y,   g_y);
    cudaGetSymbolAddress((void**)&qkv, g_qkv);
    cudaGetSymbolAddress((void**)&fc,  g_fc);
    cudaGetSymbolAddress((void**)&wh,  g_wh);

    __half* in_wh   = wh;
    __half* out_wh  = wh + W_IN_CNT;
    __half* fc_wh   = wh + W_IN_CNT + W_OUT_CNT;
    __half* proj_wh = wh + W_IN_CNT + W_OUT_CNT + W_FC_CNT;

    // 3-stage smem: wide (WN=4) = 3*16384 + 3*32768 = 147456; narrow = 98304
    const int SMEM_WIDE = 147456, SMEM_NARROW = 98304;
    cudaFuncSetAttribute(gemm_h<4, 0>, cudaFuncAttributeMaxDynamicSharedMemorySize, SMEM_WIDE);
    cudaFuncSetAttribute(gemm_h<4, 1>, cudaFuncAttributeMaxDynamicSharedMemorySize, SMEM_WIDE);
    cudaFuncSetAttribute(gemm_h<2, 2>, cudaFuncAttributeMaxDynamicSharedMemorySize, SMEM_NARROW);

    // all weight groups in one launch
    {
        int total4 = (W_IN_CNT + W_OUT_CNT + W_FC_CNT + W_PROJ_CNT) / 4;
        f2h_all_kernel<<<(total4 + 255) / 256, 256>>>(in_w, out_w, fc_w, proj_w, wh);
    }

    // fused embed + LN1 (layer 0)
    embed_ln_kernel<<<NR, 256>>>(x, date, wpe, h, y, ln1_w, ln1_b);

    for (int l = 0; l < Ll; l++) {
        if (l > 0)
            ln_kernel<__half><<<NR, 256>>>(h, y, ln1_w + (size_t)l * Ee, ln1_b + (size_t)l * Ee);
        gemm_h<4, 0><<<dim3(3 * Ee / 256, NR / 128), 256, SMEM_WIDE>>>(
            y, in_wh + (size_t)l * 3 * Ee * Ee, in_b + (size_t)l * 3 * Ee, qkv,
            NR, 3 * Ee, Ee);
        attn_mma<<<dim3(Tt, Hh, Bb), 64>>>(qkv, y);
        gemm_h<2, 2><<<dim3(Ee / 128, NR / 128), 128, SMEM_NARROW>>>(
            y, out_wh + (size_t)l * Ee * Ee, out_b + (size_t)l * Ee, h,
            NR, Ee, Ee);
        ln_kernel<__half><<<NR, 256>>>(h, y, ln2_w + (size_t)l * Ee, ln2_b + (size_t)l * Ee);
        gemm_h<4, 1><<<dim3(4 * Ee / 256, NR / 128), 256, SMEM_WIDE>>>(
            y, fc_wh + (size_t)l * 4 * Ee * Ee, fc_b + (size_t)l * 4 * Ee, fc,
            NR, 4 * Ee, Ee);
        gemm_h<2, 2><<<dim3(Ee / 128, NR / 128), 128, SMEM_NARROW>>>(
            fc, proj_wh + (size_t)l * Ee * 4 * Ee, proj_b + (size_t)l * Ee, h,
            NR, Ee, 4 * Ee);
    }

    ln_kernel<float><<<NR, 256>>>(h, out, lnf_w, lnf_b);
}